// round 1
// baseline (speedup 1.0000x reference)
#include <cuda_runtime.h>
#include <math.h>

#define TT 1024
#define BB 32
#define DD 256
#define HH 512
#define G4 2048   // 4*H
#define OO 256

// Scratch (device globals: allocation-free rule)
__device__ float g_xp[(size_t)TT * G4 * BB];   // [T][4H][B]  pre-activations (x-proj + both biases)
__device__ float g_hs[(size_t)TT * BB * HH];   // [T][B][H]   hidden states of current layer
__device__ unsigned int g_bar;                 // global barrier counter

__global__ void reset_bar_kernel() { g_bar = 0u; }

// ---------------------------------------------------------------------------
// Projection GEMM: xp[t][n][b] = sum_k W[n][k] * in(t,b,k) + bx[n] + bh[n]
// in(t,b,k) = inp[t*strideT + b*strideB + k], k contiguous.
// Grid: (16 n-tiles of 128, T). Block: 256 threads, thread tile 4n x 4b.
// ---------------------------------------------------------------------------
__global__ void proj_kernel(const float* __restrict__ W,
                            const float* __restrict__ bx,
                            const float* __restrict__ bh,
                            const float* __restrict__ inp,
                            long strideT, long strideB, int K,
                            float* __restrict__ xp)
{
    const int t   = blockIdx.y;
    const int n0  = blockIdx.x * 128;
    const int tid = threadIdx.x;
    const int ng  = tid & 31;   // 32 groups of 4 n
    const int bg  = tid >> 5;   // 8 groups of 4 b

    __shared__ float Wt[32][132];  // [k][n] transposed, padded
    __shared__ float Xt[32][36];   // [k][b] transposed, padded

    float acc[4][4];
#pragma unroll
    for (int i = 0; i < 4; i++)
#pragma unroll
        for (int j = 0; j < 4; j++) acc[i][j] = 0.f;

    const float* inT = inp + (size_t)t * strideT;

    for (int k0 = 0; k0 < K; k0 += 32) {
        __syncthreads();
        // Load W tile (128 n x 32 k), coalesced, store transposed
#pragma unroll
        for (int i = 0; i < 4; i++) {
            int f  = tid + i * 256;        // 0..1023 float4 id
            int r  = f >> 3;               // 0..127 row
            int c4 = (f & 7) * 4;          // k within chunk
            float4 v = *(const float4*)(W + (size_t)(n0 + r) * K + k0 + c4);
            Wt[c4 + 0][r] = v.x; Wt[c4 + 1][r] = v.y;
            Wt[c4 + 2][r] = v.z; Wt[c4 + 3][r] = v.w;
        }
        // Load X tile (32 b x 32 k), coalesced, store transposed
        {
            int b  = tid >> 3;
            int kq = (tid & 7) * 4;
            float4 v = *(const float4*)(inT + (size_t)b * strideB + k0 + kq);
            Xt[kq + 0][b] = v.x; Xt[kq + 1][b] = v.y;
            Xt[kq + 2][b] = v.z; Xt[kq + 3][b] = v.w;
        }
        __syncthreads();
#pragma unroll 8
        for (int k = 0; k < 32; k++) {
            float4 w = *(const float4*)&Wt[k][ng * 4];
            float4 x = *(const float4*)&Xt[k][bg * 4];
            float wv[4] = {w.x, w.y, w.z, w.w};
            float xv[4] = {x.x, x.y, x.z, x.w};
#pragma unroll
            for (int i = 0; i < 4; i++)
#pragma unroll
                for (int j = 0; j < 4; j++)
                    acc[i][j] += wv[i] * xv[j];
        }
    }

    float* outp = xp + ((size_t)t * G4 + n0) * BB;
#pragma unroll
    for (int i = 0; i < 4; i++) {
        int n = ng * 4 + i;
        float bias = bx[n0 + n] + bh[n0 + n];
        float4 v = make_float4(acc[i][0] + bias, acc[i][1] + bias,
                               acc[i][2] + bias, acc[i][3] + bias);
        *(float4*)(outp + (size_t)n * BB + bg * 4) = v;
    }
}

// ---------------------------------------------------------------------------
// Persistent LSTM recurrence. Grid 128 CTAs (1/SM), 256 threads.
// CTA owns 4 hidden units j0..j0+3 (16 gate rows: r = gate*4 + jj).
// Wh slice + cell state live in SMEM for all 1024 steps; h broadcast via L2.
// SMEM floats: WSH[512*16] + HSH[512*36] + RED[16*512] + GT[16*32] + CC[128]
// ---------------------------------------------------------------------------
#define LSTM_SMEM_FLOATS (512*16 + 512*36 + 16*512 + 16*32 + 128)
#define LSTM_SMEM_BYTES  (LSTM_SMEM_FLOATS * 4)

__global__ void lstm_kernel(const float* __restrict__ Wh,   // [4][H][H]
                            const float* __restrict__ xp,   // [T][4H][B]
                            float* __restrict__ hs)         // [T][B][H]
{
    extern __shared__ float sm[];
    float* WSH = sm;                  // [k][r] : WSH[k*16 + r]
    float* HSH = WSH + 512 * 16;      // [k][b] : HSH[k*36 + b] (padded)
    float* RED = HSH + 512 * 36;      // [ks][r][b]
    float* GT  = RED + 16 * 512;      // [r][b] staged xp
    float* CC  = GT + 16 * 32;        // [jj][b] cell state

    const int tid  = threadIdx.x;
    const int j0   = blockIdx.x * 4;
    const int ks   = tid >> 4;        // 16 k-slices of 32
    const int tile = tid & 15;
    const int rg   = tile & 1;        // 2 row groups of 8
    const int bg   = tile >> 1;       // 8 b groups of 4

    // Preload this CTA's 16 Wh rows (transposed) — resident for all steps.
    for (int f = tid; f < 16 * 128; f += 256) {     // 2048 float4s
        int r  = f >> 7;              // 0..15 : r = gidx*4 + jj
        int c4 = (f & 127) * 4;
        int gidx = r >> 2, jj = r & 3;
        float4 v = *(const float4*)(Wh + ((size_t)gidx * HH + j0 + jj) * HH + c4);
        WSH[(c4 + 0) * 16 + r] = v.x; WSH[(c4 + 1) * 16 + r] = v.y;
        WSH[(c4 + 2) * 16 + r] = v.z; WSH[(c4 + 3) * 16 + r] = v.w;
    }
    for (int i = tid; i < 512 * 36; i += 256) HSH[i] = 0.f;  // h_{-1} = 0
    if (tid < 128) CC[tid] = 0.f;                            // c_{-1} = 0
    __syncthreads();

    unsigned int target = gridDim.x;

    for (int t = 0; t < TT; t++) {
        // Load h_{t-1} (full vector, bypass L1), store transposed [k][b]
        if (t > 0) {
            int b  = tid >> 3;
            int kq = (tid & 7) * 4;
            const float* hsrc = hs + ((size_t)(t - 1) * BB + b) * HH;
#pragma unroll
            for (int i = 0; i < 16; i++) {
                int k = kq + i * 32;
                float4 v = __ldcg((const float4*)(hsrc + k));
                HSH[(k + 0) * 36 + b] = v.x; HSH[(k + 1) * 36 + b] = v.y;
                HSH[(k + 2) * 36 + b] = v.z; HSH[(k + 3) * 36 + b] = v.w;
            }
        }
        // Stage xp[t] for our 16 rows into GT
        if (tid < 128) {
            int r  = tid >> 3;          // 0..15
            int b4 = (tid & 7) * 4;
            int gidx = r >> 2, jj = r & 3;
            const float* src = xp + ((size_t)t * G4 + gidx * HH + j0 + jj) * BB + b4;
            float4 v = __ldcg((const float4*)src);
            *(float4*)&GT[r * 32 + b4] = v;
        }
        __syncthreads();

        // Partial gate GEMM: 8 rows x 4 b per thread over a 32-wide k slice
        float acc[8][4];
#pragma unroll
        for (int i = 0; i < 8; i++)
#pragma unroll
            for (int j = 0; j < 4; j++) acc[i][j] = 0.f;

        const int kbase = ks * 32;
#pragma unroll 4
        for (int kk = 0; kk < 32; kk++) {
            int k = kbase + kk;
            float4 h4 = *(const float4*)&HSH[k * 36 + bg * 4];
            float4 w0 = *(const float4*)&WSH[k * 16 + rg * 8];
            float4 w1 = *(const float4*)&WSH[k * 16 + rg * 8 + 4];
            float hv[4] = {h4.x, h4.y, h4.z, h4.w};
            float wv[8] = {w0.x, w0.y, w0.z, w0.w, w1.x, w1.y, w1.z, w1.w};
#pragma unroll
            for (int i = 0; i < 8; i++)
#pragma unroll
                for (int j = 0; j < 4; j++)
                    acc[i][j] += wv[i] * hv[j];
        }
#pragma unroll
        for (int i = 0; i < 8; i++) {
            int r = rg * 8 + i;
            *(float4*)&RED[ks * 512 + r * 32 + bg * 4] =
                make_float4(acc[i][0], acc[i][1], acc[i][2], acc[i][3]);
        }
        __syncthreads();

        // Reduce over 16 k-slices + activations + state update (128 threads)
        if (tid < 128) {
            int b  = tid & 31;
            int jj = tid >> 5;
            float gv[4];
#pragma unroll
            for (int gidx = 0; gidx < 4; gidx++) {
                int r = gidx * 4 + jj;
                float s = GT[r * 32 + b];
#pragma unroll
                for (int kss = 0; kss < 16; kss++) s += RED[kss * 512 + r * 32 + b];
                gv[gidx] = s;
            }
            float gg = tanhf(gv[0]);
            float ii = 1.f / (1.f + __expf(-gv[1]));
            float ff = 1.f / (1.f + __expf(-gv[2]));
            float oo = 1.f / (1.f + __expf(-gv[3]));
            float c  = ff * CC[jj * 32 + b] + ii * gg;
            CC[jj * 32 + b] = c;
            float h = oo * tanhf(c);
            hs[((size_t)t * BB + b) * HH + j0 + jj] = h;
        }

        // Grid-wide barrier: publish h_t, then wait for all CTAs
        __syncthreads();
        if (tid == 0) {
            __threadfence();                       // release: drain h stores to L2
            atomicAdd(&g_bar, 1u);
            while (*(volatile unsigned int*)&g_bar < target) { __nanosleep(64); }
        }
        target += gridDim.x;
        __syncthreads();
        __threadfence();                           // acquire: invalidate L1 before next h load
    }
}

// ---------------------------------------------------------------------------
// Final FC: out[b][o] = sum_k hs[T-1][b][k] * fcW[o][k] + fcb[o]
// ---------------------------------------------------------------------------
__global__ void fc_kernel(const float* __restrict__ fcW,
                          const float* __restrict__ fcb,
                          float* __restrict__ out)
{
    const int b = blockIdx.x;
    const int o = threadIdx.x;     // 256 threads
    __shared__ float hsh[HH];
    const float* h = g_hs + ((size_t)(TT - 1) * BB + b) * HH;
    for (int k = threadIdx.x; k < HH; k += blockDim.x) hsh[k] = h[k];
    __syncthreads();
    float acc = 0.f;
    const float* w = fcW + (size_t)o * HH;
#pragma unroll 8
    for (int k = 0; k < HH; k += 4) {
        float4 wv = *(const float4*)(w + k);
        acc += wv.x * hsh[k] + wv.y * hsh[k + 1] + wv.z * hsh[k + 2] + wv.w * hsh[k + 3];
    }
    out[(size_t)b * OO + o] = acc + fcb[o];
}

// ---------------------------------------------------------------------------
extern "C" void kernel_launch(void* const* d_in, const int* in_sizes, int n_in,
                              void* d_out, int out_size)
{
    const float* x   = (const float*)d_in[0];
    const float* Wx0 = (const float*)d_in[1];
    const float* bx0 = (const float*)d_in[2];
    const float* Wh0 = (const float*)d_in[3];
    const float* bh0 = (const float*)d_in[4];
    const float* Wx1 = (const float*)d_in[5];
    const float* bx1 = (const float*)d_in[6];
    const float* Wh1 = (const float*)d_in[7];
    const float* bh1 = (const float*)d_in[8];
    const float* fcW = (const float*)d_in[9];
    const float* fcb = (const float*)d_in[10];
    float* out = (float*)d_out;
    (void)in_sizes; (void)n_in; (void)out_size;

    float* xp = nullptr; cudaGetSymbolAddress((void**)&xp, g_xp);
    float* hs = nullptr; cudaGetSymbolAddress((void**)&hs, g_hs);

    cudaFuncSetAttribute(lstm_kernel,
                         cudaFuncAttributeMaxDynamicSharedMemorySize,
                         LSTM_SMEM_BYTES);

    dim3 gproj(16, TT);

    // Layer 0: x is [B][T][D] -> in(t,b,k) strides: t->D, b->T*D
    proj_kernel<<<gproj, 256>>>(Wx0, bx0, bh0, x, (long)DD, (long)TT * DD, DD, xp);
    reset_bar_kernel<<<1, 1>>>();
    lstm_kernel<<<128, 256, LSTM_SMEM_BYTES>>>(Wh0, xp, hs);

    // Layer 1: hs is [T][B][H] -> strides: t->B*H, b->H
    proj_kernel<<<gproj, 256>>>(Wx1, bx1, bh1, hs, (long)BB * HH, (long)HH, HH, xp);
    reset_bar_kernel<<<1, 1>>>();
    lstm_kernel<<<128, 256, LSTM_SMEM_BYTES>>>(Wh1, xp, hs);

    fc_kernel<<<BB, 256>>>(fcW, fcb, out);
}

// round 2
// speedup vs baseline: 1.1462x; 1.1462x over previous
#include <cuda_runtime.h>
#include <math.h>

#define TT 1024
#define BB 32
#define DD 256
#define HH 512
#define G4 2048   // 4*H
#define OO 256

typedef unsigned long long u64;

// ---- packed fp32x2 helpers (sm_103a FFMA2 path, exact fp32 numerics) ----
__device__ __forceinline__ u64 ffma2(u64 a, u64 b, u64 c) {
    u64 d; asm("fma.rn.f32x2 %0, %1, %2, %3;" : "=l"(d) : "l"(a), "l"(b), "l"(c)); return d;
}
__device__ __forceinline__ u64 dup2(float x) {
    u64 d; unsigned xi = __float_as_uint(x);
    asm("mov.b64 %0, {%1, %1};" : "=l"(d) : "r"(xi)); return d;
}
__device__ __forceinline__ float2 unpk(u64 a) {
    unsigned lo, hi; asm("mov.b64 {%0, %1}, %2;" : "=r"(lo), "=r"(hi) : "l"(a));
    return make_float2(__uint_as_float(lo), __uint_as_float(hi));
}

// Scratch (device globals: allocation-free rule)
__device__ float g_xp[(size_t)TT * G4 * BB];   // [T][4H][B] pre-activations (+ both biases)
__device__ float g_hs[(size_t)TT * BB * HH];   // [T][B][H]  hidden states of current layer
__device__ unsigned int g_bar;

__global__ void reset_bar_kernel() { g_bar = 0u; }

// ---------------------------------------------------------------------------
// Projection GEMM over flat M=(t,b)=T*B: xp[t][n][b] = sum_k W[n][k]*in(t,b,k)+bias
// Tile: 256n x 64m (2 timesteps), K-tile 16. Block 256 thr, thread tile 8n x 8m.
// Grid: (G4/256=8, T/2=512).
// ---------------------------------------------------------------------------
__global__ void __launch_bounds__(256, 2)
proj_kernel(const float* __restrict__ W,
            const float* __restrict__ bx,
            const float* __restrict__ bh,
            const float* __restrict__ inp,
            long strideT, long strideB, int K,
            float* __restrict__ xp)
{
    const int n0  = blockIdx.x * 256;
    const int t0  = blockIdx.y * 2;
    const int tid = threadIdx.x;
    const int ng  = tid >> 3;   // 0..31 -> n = n0 + ng*8
    const int mg  = tid & 7;    // 0..7  -> m = mg*8

    __shared__ float Wt[16][264];  // [k][n], padded
    __shared__ float Xt[16][72];   // [k][m], padded

    u64 acc[4][8];   // [n-pair][m]
#pragma unroll
    for (int i = 0; i < 4; i++)
#pragma unroll
        for (int j = 0; j < 8; j++) acc[i][j] = 0ULL;

    // X load indices (fixed per thread)
    const int xm  = tid >> 2;           // 0..63
    const int xc4 = (tid & 3) * 4;      // k offset
    const int xt  = t0 + (xm >> 5);
    const int xb  = xm & 31;
    const float* xsrc = inp + (size_t)xt * strideT + (size_t)xb * strideB + xc4;

    for (int k0 = 0; k0 < K; k0 += 16) {
        __syncthreads();
        // W tile: 256n x 16k -> 1024 float4, 4 per thread
#pragma unroll
        for (int i = 0; i < 4; i++) {
            int f  = tid + i * 256;
            int r  = f >> 2;
            int c4 = (f & 3) * 4;
            float4 v = *(const float4*)(W + (size_t)(n0 + r) * K + k0 + c4);
            Wt[c4 + 0][r] = v.x; Wt[c4 + 1][r] = v.y;
            Wt[c4 + 2][r] = v.z; Wt[c4 + 3][r] = v.w;
        }
        // X tile: 64m x 16k -> 256 float4, 1 per thread
        {
            float4 v = *(const float4*)(xsrc + k0);
            Xt[xc4 + 0][xm] = v.x; Xt[xc4 + 1][xm] = v.y;
            Xt[xc4 + 2][xm] = v.z; Xt[xc4 + 3][xm] = v.w;
        }
        __syncthreads();

#pragma unroll
        for (int k = 0; k < 16; k++) {
            const ulonglong2* wp = (const ulonglong2*)&Wt[k][ng * 8];
            ulonglong2 wA = wp[0];   // pairs (n+0,n+1),(n+2,n+3)
            ulonglong2 wB = wp[1];   // pairs (n+4,n+5),(n+6,n+7)
            float4 x0 = *(const float4*)&Xt[k][mg * 8];
            float4 x1 = *(const float4*)&Xt[k][mg * 8 + 4];
            u64 xd[8] = {dup2(x0.x), dup2(x0.y), dup2(x0.z), dup2(x0.w),
                         dup2(x1.x), dup2(x1.y), dup2(x1.z), dup2(x1.w)};
            u64 wv[4] = {wA.x, wA.y, wB.x, wB.y};
#pragma unroll
            for (int i = 0; i < 4; i++)
#pragma unroll
                for (int j = 0; j < 8; j++)
                    acc[i][j] = ffma2(wv[i], xd[j], acc[i][j]);
        }
    }

    // Epilogue: bias + store (8 consecutive b per thread, one t)
    float bias[8];
#pragma unroll
    for (int r = 0; r < 8; r++) {
        int n = n0 + ng * 8 + r;
        bias[r] = bx[n] + bh[n];
    }
    const int ot = t0 + (mg >> 2);
    const int ob = (mg & 3) * 8;
    float* outb = xp + ((size_t)ot * G4 + n0 + ng * 8) * BB + ob;
#pragma unroll
    for (int i = 0; i < 4; i++) {
        float2 p[8];
#pragma unroll
        for (int j = 0; j < 8; j++) p[j] = unpk(acc[i][j]);
        int rlo = 2 * i, rhi = 2 * i + 1;
        *(float4*)(outb + (size_t)rlo * BB)     = make_float4(p[0].x + bias[rlo], p[1].x + bias[rlo], p[2].x + bias[rlo], p[3].x + bias[rlo]);
        *(float4*)(outb + (size_t)rlo * BB + 4) = make_float4(p[4].x + bias[rlo], p[5].x + bias[rlo], p[6].x + bias[rlo], p[7].x + bias[rlo]);
        *(float4*)(outb + (size_t)rhi * BB)     = make_float4(p[0].y + bias[rhi], p[1].y + bias[rhi], p[2].y + bias[rhi], p[3].y + bias[rhi]);
        *(float4*)(outb + (size_t)rhi * BB + 4) = make_float4(p[4].y + bias[rhi], p[5].y + bias[rhi], p[6].y + bias[rhi], p[7].y + bias[rhi]);
    }
}

// ---------------------------------------------------------------------------
// Persistent LSTM recurrence. 128 CTAs (1/SM), 256 threads. FFMA2 inner loop.
// ---------------------------------------------------------------------------
#define LSTM_SMEM_FLOATS (512*16 + 512*36 + 16*512 + 16*32 + 128)
#define LSTM_SMEM_BYTES  (LSTM_SMEM_FLOATS * 4)

__global__ void __launch_bounds__(256, 1)
lstm_kernel(const float* __restrict__ Wh,   // [4][H][H]
            const float* __restrict__ xp,   // [T][4H][B]
            float* __restrict__ hs)         // [T][B][H]
{
    extern __shared__ float sm[];
    float* WSH = sm;                  // [k][r] : WSH[k*16 + r]
    float* HSH = WSH + 512 * 16;      // [k][b] : HSH[k*36 + b]
    float* RED = HSH + 512 * 36;      // [ks][r][b]
    float* GT  = RED + 16 * 512;      // [r][b]
    float* CC  = GT + 16 * 32;        // [jj][b]

    const int tid  = threadIdx.x;
    const int j0   = blockIdx.x * 4;
    const int ks   = tid >> 4;        // 16 k-slices of 32
    const int tile = tid & 15;
    const int rg   = tile & 1;        // 2 row groups of 8
    const int bg   = tile >> 1;       // 8 b groups of 4

    // Preload Wh rows transposed (resident all steps)
    for (int f = tid; f < 16 * 128; f += 256) {
        int r  = f >> 7;
        int c4 = (f & 127) * 4;
        int gidx = r >> 2, jj = r & 3;
        float4 v = *(const float4*)(Wh + ((size_t)gidx * HH + j0 + jj) * HH + c4);
        WSH[(c4 + 0) * 16 + r] = v.x; WSH[(c4 + 1) * 16 + r] = v.y;
        WSH[(c4 + 2) * 16 + r] = v.z; WSH[(c4 + 3) * 16 + r] = v.w;
    }
    for (int i = tid; i < 512 * 36; i += 256) HSH[i] = 0.f;
    if (tid < 128) CC[tid] = 0.f;
    __syncthreads();

    unsigned int target = gridDim.x;

    for (int t = 0; t < TT; t++) {
        if (t > 0) {
            int b  = tid >> 3;
            int kq = (tid & 7) * 4;
            const float* hsrc = hs + ((size_t)(t - 1) * BB + b) * HH;
#pragma unroll
            for (int i = 0; i < 16; i++) {
                int k = kq + i * 32;
                float4 v = __ldcg((const float4*)(hsrc + k));
                HSH[(k + 0) * 36 + b] = v.x; HSH[(k + 1) * 36 + b] = v.y;
                HSH[(k + 2) * 36 + b] = v.z; HSH[(k + 3) * 36 + b] = v.w;
            }
        }
        if (tid < 128) {
            int r  = tid >> 3;
            int b4 = (tid & 7) * 4;
            int gidx = r >> 2, jj = r & 3;
            const float* src = xp + ((size_t)t * G4 + gidx * HH + j0 + jj) * BB + b4;
            float4 v = __ldcg((const float4*)src);
            *(float4*)&GT[r * 32 + b4] = v;
        }
        __syncthreads();

        // FFMA2 partial GEMM: pairs over rows, 8r x 4b per thread, 32-wide k slice
        u64 acc2[4][4];
#pragma unroll
        for (int i = 0; i < 4; i++)
#pragma unroll
            for (int j = 0; j < 4; j++) acc2[i][j] = 0ULL;

        const int kbase = ks * 32;
#pragma unroll 8
        for (int kk = 0; kk < 32; kk++) {
            int k = kbase + kk;
            const ulonglong2* wp = (const ulonglong2*)&WSH[k * 16 + rg * 8];
            ulonglong2 wA = wp[0];
            ulonglong2 wB = wp[1];
            float4 h4 = *(const float4*)&HSH[k * 36 + bg * 4];
            u64 hd[4] = {dup2(h4.x), dup2(h4.y), dup2(h4.z), dup2(h4.w)};
            u64 wv[4] = {wA.x, wA.y, wB.x, wB.y};
#pragma unroll
            for (int i = 0; i < 4; i++)
#pragma unroll
                for (int j = 0; j < 4; j++)
                    acc2[i][j] = ffma2(wv[i], hd[j], acc2[i][j]);
        }
#pragma unroll
        for (int i = 0; i < 4; i++) {
            float2 p0 = unpk(acc2[i][0]), p1 = unpk(acc2[i][1]);
            float2 p2 = unpk(acc2[i][2]), p3 = unpk(acc2[i][3]);
            int r0 = rg * 8 + 2 * i, r1 = r0 + 1;
            *(float4*)&RED[ks * 512 + r0 * 32 + bg * 4] = make_float4(p0.x, p1.x, p2.x, p3.x);
            *(float4*)&RED[ks * 512 + r1 * 32 + bg * 4] = make_float4(p0.y, p1.y, p2.y, p3.y);
        }
        __syncthreads();

        // Reduce + activations + state update
        if (tid < 128) {
            int b  = tid & 31;
            int jj = tid >> 5;
            float gv[4];
#pragma unroll
            for (int gidx = 0; gidx < 4; gidx++) {
                int r = gidx * 4 + jj;
                float s = GT[r * 32 + b];
#pragma unroll
                for (int kss = 0; kss < 16; kss++) s += RED[kss * 512 + r * 32 + b];
                gv[gidx] = s;
            }
            float gg = tanhf(gv[0]);
            float ii = 1.f / (1.f + __expf(-gv[1]));
            float ff = 1.f / (1.f + __expf(-gv[2]));
            float oo = 1.f / (1.f + __expf(-gv[3]));
            float c  = ff * CC[jj * 32 + b] + ii * gg;
            CC[jj * 32 + b] = c;
            float h = oo * tanhf(c);
            hs[((size_t)t * BB + b) * HH + j0 + jj] = h;
        }

        __syncthreads();
        if (tid == 0) {
            __threadfence();
            atomicAdd(&g_bar, 1u);
            while (*(volatile unsigned int*)&g_bar < target) { __nanosleep(64); }
        }
        target += gridDim.x;
        __syncthreads();
        __threadfence();
    }
}

// ---------------------------------------------------------------------------
__global__ void fc_kernel(const float* __restrict__ fcW,
                          const float* __restrict__ fcb,
                          float* __restrict__ out)
{
    const int b = blockIdx.x;
    const int o = threadIdx.x;
    __shared__ float hsh[HH];
    const float* h = g_hs + ((size_t)(TT - 1) * BB + b) * HH;
    for (int k = threadIdx.x; k < HH; k += blockDim.x) hsh[k] = h[k];
    __syncthreads();
    float acc = 0.f;
    const float* w = fcW + (size_t)o * HH;
#pragma unroll 8
    for (int k = 0; k < HH; k += 4) {
        float4 wv = *(const float4*)(w + k);
        acc += wv.x * hsh[k] + wv.y * hsh[k + 1] + wv.z * hsh[k + 2] + wv.w * hsh[k + 3];
    }
    out[(size_t)b * OO + o] = acc + fcb[o];
}

// ---------------------------------------------------------------------------
extern "C" void kernel_launch(void* const* d_in, const int* in_sizes, int n_in,
                              void* d_out, int out_size)
{
    const float* x   = (const float*)d_in[0];
    const float* Wx0 = (const float*)d_in[1];
    const float* bx0 = (const float*)d_in[2];
    const float* Wh0 = (const float*)d_in[3];
    const float* bh0 = (const float*)d_in[4];
    const float* Wx1 = (const float*)d_in[5];
    const float* bx1 = (const float*)d_in[6];
    const float* Wh1 = (const float*)d_in[7];
    const float* bh1 = (const float*)d_in[8];
    const float* fcW = (const float*)d_in[9];
    const float* fcb = (const float*)d_in[10];
    float* out = (float*)d_out;
    (void)in_sizes; (void)n_in; (void)out_size;

    float* xp = nullptr; cudaGetSymbolAddress((void**)&xp, g_xp);
    float* hs = nullptr; cudaGetSymbolAddress((void**)&hs, g_hs);

    cudaFuncSetAttribute(lstm_kernel,
                         cudaFuncAttributeMaxDynamicSharedMemorySize,
                         LSTM_SMEM_BYTES);

    dim3 gproj(G4 / 256, TT / 2);

    // Layer 0: x is [B][T][D] -> in(t,b,k): t->D, b->T*D
    proj_kernel<<<gproj, 256>>>(Wx0, bx0, bh0, x, (long)DD, (long)TT * DD, DD, xp);
    reset_bar_kernel<<<1, 1>>>();
    lstm_kernel<<<128, 256, LSTM_SMEM_BYTES>>>(Wh0, xp, hs);

    // Layer 1: hs is [T][B][H] -> t->B*H, b->H
    proj_kernel<<<gproj, 256>>>(Wx1, bx1, bh1, hs, (long)BB * HH, (long)HH, HH, xp);
    reset_bar_kernel<<<1, 1>>>();
    lstm_kernel<<<128, 256, LSTM_SMEM_BYTES>>>(Wh1, xp, hs);

    fc_kernel<<<BB, 256>>>(fcW, fcb, out);
}

// round 3
// speedup vs baseline: 1.2378x; 1.0799x over previous
#include <cuda_runtime.h>
#include <math.h>

#define TT 1024
#define BB 32
#define DD 256
#define HH 512
#define G4 2048   // 4*H
#define OO 256
#define MM (TT * BB)   // 32768 flat (t,b)

typedef unsigned long long u64;

// ---- packed fp32x2 helpers (sm_103a FFMA2, exact fp32 numerics) ----
__device__ __forceinline__ u64 ffma2(u64 a, u64 b, u64 c) {
    u64 d; asm("fma.rn.f32x2 %0, %1, %2, %3;" : "=l"(d) : "l"(a), "l"(b), "l"(c)); return d;
}
__device__ __forceinline__ u64 dup2(float x) {
    u64 d; unsigned xi = __float_as_uint(x);
    asm("mov.b64 %0, {%1, %1};" : "=l"(d) : "r"(xi)); return d;
}
__device__ __forceinline__ float2 unpk(u64 a) {
    unsigned lo, hi; asm("mov.b64 {%0, %1}, %2;" : "=r"(lo), "=r"(hi) : "l"(a));
    return make_float2(__uint_as_float(lo), __uint_as_float(hi));
}

// Scratch (device globals: allocation-free rule)
__device__ float g_xp[(size_t)TT * G4 * BB];   // [T][4H][B] pre-activations (+ biases)
__device__ float g_hs[(size_t)TT * BB * HH];   // [T][B][H]  hidden states (b-major rows)
__device__ float g_xt[(size_t)HH * MM];        // [K][T*B]   k-major proj input (x, then h)
__device__ float g_wt[(size_t)HH * G4];        // [K][4H]    k-major weights (per layer)
__device__ unsigned int g_bar;

__global__ void reset_bar_kernel() { g_bar = 0u; }

// ---------------------------------------------------------------------------
// Transpose x[B][T][D] -> xt[D][T*32 + b]. Grid (T, D/32), 256 threads.
// ---------------------------------------------------------------------------
__global__ void transpose_x_kernel(const float* __restrict__ x, float* __restrict__ xt)
{
    const int t  = blockIdx.x;
    const int d0 = blockIdx.y * 32;
    const int tid = threadIdx.x;
    __shared__ float s[32][36];
    {
        int b  = tid >> 3;
        int d4 = (tid & 7) * 4;
        float4 v = *(const float4*)(x + (size_t)b * TT * DD + (size_t)t * DD + d0 + d4);
        s[b][d4 + 0] = v.x; s[b][d4 + 1] = v.y; s[b][d4 + 2] = v.z; s[b][d4 + 3] = v.w;
    }
    __syncthreads();
    {
        int d  = tid >> 3;
        int b4 = (tid & 7) * 4;
        float4 o = make_float4(s[b4 + 0][d], s[b4 + 1][d], s[b4 + 2][d], s[b4 + 3][d]);
        *(float4*)(xt + (size_t)(d0 + d) * MM + (size_t)t * BB + b4) = o;
    }
}

// ---------------------------------------------------------------------------
// Transpose W[2048][K] -> wt[K][2048]. Grid (2048/32, K/32), 256 threads.
// ---------------------------------------------------------------------------
__global__ void transpose_w_kernel(const float* __restrict__ W, float* __restrict__ wt, int K)
{
    const int n0 = blockIdx.x * 32;
    const int k0 = blockIdx.y * 32;
    const int tid = threadIdx.x;
    __shared__ float s[32][36];
    {
        int n  = tid >> 3;
        int k4 = (tid & 7) * 4;
        float4 v = *(const float4*)(W + (size_t)(n0 + n) * K + k0 + k4);
        s[n][k4 + 0] = v.x; s[n][k4 + 1] = v.y; s[n][k4 + 2] = v.z; s[n][k4 + 3] = v.w;
    }
    __syncthreads();
    {
        int k  = tid >> 3;
        int n4 = (tid & 7) * 4;
        float4 o = make_float4(s[n4 + 0][k], s[n4 + 1][k], s[n4 + 2][k], s[n4 + 3][k]);
        *(float4*)(wt + (size_t)(k0 + k) * G4 + n0 + n4) = o;
    }
}

// ---------------------------------------------------------------------------
// Projection GEMM (all k-major, conflict-free smem):
// xp[t][n][b] = sum_k wt[k][n] * xt[k][m] + bias,  m = t*32+b
// Tile 256n x 64m, K-tile 16, 256 threads, thread tile 8n x 8m (FFMA2 over n).
// ---------------------------------------------------------------------------
__global__ void __launch_bounds__(256, 2)
proj_kernel(const float* __restrict__ wt,
            const float* __restrict__ bx,
            const float* __restrict__ bh,
            const float* __restrict__ xt,
            int K,
            float* __restrict__ xp)
{
    const int n0  = blockIdx.x * 256;
    const int m0  = blockIdx.y * 64;
    const int tid = threadIdx.x;
    const int ng  = tid >> 3;   // 0..31
    const int mg  = tid & 7;    // 0..7

    __shared__ float Ws[16][264];
    __shared__ float Xs[16][72];

    u64 acc[4][8];
#pragma unroll
    for (int i = 0; i < 4; i++)
#pragma unroll
        for (int j = 0; j < 8; j++) acc[i][j] = 0ULL;

    const int xk  = tid >> 4;          // 0..15
    const int xm4 = (tid & 15) * 4;

    for (int k0 = 0; k0 < K; k0 += 16) {
        __syncthreads();
        // W tile: 16k x 256n, direct float4 (coalesced gmem, conflict-free smem)
#pragma unroll
        for (int i = 0; i < 4; i++) {
            int id = i * 256 + tid;
            int k  = id >> 6;
            int n4 = (id & 63) * 4;
            float4 v = *(const float4*)(wt + (size_t)(k0 + k) * G4 + n0 + n4);
            *(float4*)&Ws[k][n4] = v;
        }
        // X tile: 16k x 64m
        {
            float4 v = *(const float4*)(xt + (size_t)(k0 + xk) * MM + m0 + xm4);
            *(float4*)&Xs[xk][xm4] = v;
        }
        __syncthreads();

#pragma unroll
        for (int k = 0; k < 16; k++) {
            const ulonglong2* wp = (const ulonglong2*)&Ws[k][ng * 8];
            ulonglong2 wA = wp[0];
            ulonglong2 wB = wp[1];
            float4 x0 = *(const float4*)&Xs[k][mg * 8];
            float4 x1 = *(const float4*)&Xs[k][mg * 8 + 4];
            u64 xd[8] = {dup2(x0.x), dup2(x0.y), dup2(x0.z), dup2(x0.w),
                         dup2(x1.x), dup2(x1.y), dup2(x1.z), dup2(x1.w)};
            u64 wv[4] = {wA.x, wA.y, wB.x, wB.y};
#pragma unroll
            for (int i = 0; i < 4; i++)
#pragma unroll
                for (int j = 0; j < 8; j++)
                    acc[i][j] = ffma2(wv[i], xd[j], acc[i][j]);
        }
    }

    float bias[8];
#pragma unroll
    for (int r = 0; r < 8; r++) {
        int n = n0 + ng * 8 + r;
        bias[r] = bx[n] + bh[n];
    }
    const int ot = (m0 >> 5) + (mg >> 2);
    const int ob = (mg & 3) * 8;
    float* outb = xp + ((size_t)ot * G4 + n0 + ng * 8) * BB + ob;
#pragma unroll
    for (int i = 0; i < 4; i++) {
        float2 p[8];
#pragma unroll
        for (int j = 0; j < 8; j++) p[j] = unpk(acc[i][j]);
        int rlo = 2 * i, rhi = 2 * i + 1;
        *(float4*)(outb + (size_t)rlo * BB)     = make_float4(p[0].x + bias[rlo], p[1].x + bias[rlo], p[2].x + bias[rlo], p[3].x + bias[rlo]);
        *(float4*)(outb + (size_t)rlo * BB + 4) = make_float4(p[4].x + bias[rlo], p[5].x + bias[rlo], p[6].x + bias[rlo], p[7].x + bias[rlo]);
        *(float4*)(outb + (size_t)rhi * BB)     = make_float4(p[0].y + bias[rhi], p[1].y + bias[rhi], p[2].y + bias[rhi], p[3].y + bias[rhi]);
        *(float4*)(outb + (size_t)rhi * BB + 4) = make_float4(p[4].y + bias[rhi], p[5].y + bias[rhi], p[6].y + bias[rhi], p[7].y + bias[rhi]);
    }
}

// ---------------------------------------------------------------------------
// Persistent LSTM recurrence. 128 CTAs (1/SM), 256 threads. FFMA2 inner loop.
// ---------------------------------------------------------------------------
#define LSTM_SMEM_FLOATS (512*16 + 512*36 + 16*512 + 16*32 + 128)
#define LSTM_SMEM_BYTES  (LSTM_SMEM_FLOATS * 4)

__global__ void __launch_bounds__(256, 1)
lstm_kernel(const float* __restrict__ Wh,   // [4][H][H]
            const float* __restrict__ xp,   // [T][4H][B]
            float* __restrict__ hs,         // [T][B][H]
            float* __restrict__ ht)         // [H][T*B] (k-major copy) or null
{
    extern __shared__ float sm[];
    float* WSH = sm;                  // [k][r]
    float* HSH = WSH + 512 * 16;      // [k][b] padded 36
    float* RED = HSH + 512 * 36;      // [ks][r][b]
    float* GT  = RED + 16 * 512;      // [r][b]
    float* CC  = GT + 16 * 32;        // [jj][b]

    const int tid  = threadIdx.x;
    const int j0   = blockIdx.x * 4;
    const int ks   = tid >> 4;
    const int tile = tid & 15;
    const int rg   = tile & 1;
    const int bg   = tile >> 1;

    // Preload Wh rows transposed (one-time; conflicts irrelevant)
    for (int f = tid; f < 16 * 128; f += 256) {
        int r  = f >> 7;
        int c4 = (f & 127) * 4;
        int gidx = r >> 2, jj = r & 3;
        float4 v = *(const float4*)(Wh + ((size_t)gidx * HH + j0 + jj) * HH + c4);
        WSH[(c4 + 0) * 16 + r] = v.x; WSH[(c4 + 1) * 16 + r] = v.y;
        WSH[(c4 + 2) * 16 + r] = v.z; WSH[(c4 + 3) * 16 + r] = v.w;
    }
    for (int i = tid; i < 512 * 36; i += 256) HSH[i] = 0.f;
    if (tid < 128) CC[tid] = 0.f;
    __syncthreads();

    const int hb  = tid >> 3;          // 0..31 (h-load batch row)
    const int hkq = (tid & 7) * 4;
    const int gr  = tid >> 3;          // 0..15 (xp row, tid<128)
    const int gb4 = (tid & 7) * 4;
    const int ggi = gr >> 2, gjj = gr & 3;

    unsigned int target = gridDim.x;

    for (int t = 0; t < TT; t++) {
        // 1) xp prefetch first (DRAM latency)
        float4 xpv;
        if (tid < 128) {
            const float* src = xp + ((size_t)t * G4 + ggi * HH + j0 + gjj) * BB + gb4;
            xpv = __ldcg((const float4*)src);
        }
        // 2) h_{t-1}: batch all 16 LDG.CG, then STS
        if (t > 0) {
            const float* hsrc = hs + ((size_t)(t - 1) * BB + hb) * HH;
            float4 hv[16];
#pragma unroll
            for (int i = 0; i < 16; i++)
                hv[i] = __ldcg((const float4*)(hsrc + hkq + i * 32));
#pragma unroll
            for (int i = 0; i < 16; i++) {
                int k = hkq + i * 32;
                HSH[(k + 0) * 36 + hb] = hv[i].x; HSH[(k + 1) * 36 + hb] = hv[i].y;
                HSH[(k + 2) * 36 + hb] = hv[i].z; HSH[(k + 3) * 36 + hb] = hv[i].w;
            }
        }
        if (tid < 128) *(float4*)&GT[gr * 32 + gb4] = xpv;
        __syncthreads();

        // 3) FFMA2 partial gate GEMM (8r x 4b per thread, 32-wide k slice)
        u64 acc2[4][4];
#pragma unroll
        for (int i = 0; i < 4; i++)
#pragma unroll
            for (int j = 0; j < 4; j++) acc2[i][j] = 0ULL;

        const int kbase = ks * 32;
#pragma unroll 8
        for (int kk = 0; kk < 32; kk++) {
            int k = kbase + kk;
            const ulonglong2* wp = (const ulonglong2*)&WSH[k * 16 + rg * 8];
            ulonglong2 wA = wp[0];
            ulonglong2 wB = wp[1];
            float4 h4 = *(const float4*)&HSH[k * 36 + bg * 4];
            u64 hd[4] = {dup2(h4.x), dup2(h4.y), dup2(h4.z), dup2(h4.w)};
            u64 wv[4] = {wA.x, wA.y, wB.x, wB.y};
#pragma unroll
            for (int i = 0; i < 4; i++)
#pragma unroll
                for (int j = 0; j < 4; j++)
                    acc2[i][j] = ffma2(wv[i], hd[j], acc2[i][j]);
        }
#pragma unroll
        for (int i = 0; i < 4; i++) {
            float2 p0 = unpk(acc2[i][0]), p1 = unpk(acc2[i][1]);
            float2 p2 = unpk(acc2[i][2]), p3 = unpk(acc2[i][3]);
            int r0 = rg * 8 + 2 * i, r1 = r0 + 1;
            *(float4*)&RED[ks * 512 + r0 * 32 + bg * 4] = make_float4(p0.x, p1.x, p2.x, p3.x);
            *(float4*)&RED[ks * 512 + r1 * 32 + bg * 4] = make_float4(p0.y, p1.y, p2.y, p3.y);
        }
        __syncthreads();

        // 4) Reduce + activations + state update
        if (tid < 128) {
            int b  = tid & 31;
            int jj = tid >> 5;
            float gv[4];
#pragma unroll
            for (int gidx = 0; gidx < 4; gidx++) {
                int r = gidx * 4 + jj;
                float s = GT[r * 32 + b];
#pragma unroll
                for (int kss = 0; kss < 16; kss++) s += RED[kss * 512 + r * 32 + b];
                gv[gidx] = s;
            }
            float gg = tanhf(gv[0]);
            float ii = 1.f / (1.f + __expf(-gv[1]));
            float ff = 1.f / (1.f + __expf(-gv[2]));
            float oo = 1.f / (1.f + __expf(-gv[3]));
            float c  = ff * CC[jj * 32 + b] + ii * gg;
            CC[jj * 32 + b] = c;
            float h = oo * tanhf(c);
            hs[((size_t)t * BB + b) * HH + j0 + jj] = h;
            if (ht) ht[(size_t)(j0 + jj) * MM + (size_t)t * BB + b] = h;  // coalesced
        }

        // 5) Grid barrier (release fence + atomic; no acquire CCTL)
        __syncthreads();
        if (tid == 0) {
            __threadfence();
            atomicAdd(&g_bar, 1u);
            while (*(volatile unsigned int*)&g_bar < target) { __nanosleep(64); }
        }
        target += gridDim.x;
        __syncthreads();
    }
}

// ---------------------------------------------------------------------------
__global__ void fc_kernel(const float* __restrict__ fcW,
                          const float* __restrict__ fcb,
                          float* __restrict__ out)
{
    const int b = blockIdx.x;
    const int o = threadIdx.x;
    __shared__ float hsh[HH];
    const float* h = g_hs + ((size_t)(TT - 1) * BB + b) * HH;
    for (int k = threadIdx.x; k < HH; k += blockDim.x) hsh[k] = h[k];
    __syncthreads();
    float acc = 0.f;
    const float* w = fcW + (size_t)o * HH;
#pragma unroll 8
    for (int k = 0; k < HH; k += 4) {
        float4 wv = *(const float4*)(w + k);
        acc += wv.x * hsh[k] + wv.y * hsh[k + 1] + wv.z * hsh[k + 2] + wv.w * hsh[k + 3];
    }
    out[(size_t)b * OO + o] = acc + fcb[o];
}

// ---------------------------------------------------------------------------
extern "C" void kernel_launch(void* const* d_in, const int* in_sizes, int n_in,
                              void* d_out, int out_size)
{
    const float* x   = (const float*)d_in[0];
    const float* Wx0 = (const float*)d_in[1];
    const float* bx0 = (const float*)d_in[2];
    const float* Wh0 = (const float*)d_in[3];
    const float* bh0 = (const float*)d_in[4];
    const float* Wx1 = (const float*)d_in[5];
    const float* bx1 = (const float*)d_in[6];
    const float* Wh1 = (const float*)d_in[7];
    const float* bh1 = (const float*)d_in[8];
    const float* fcW = (const float*)d_in[9];
    const float* fcb = (const float*)d_in[10];
    float* out = (float*)d_out;
    (void)in_sizes; (void)n_in; (void)out_size;

    float* xp = nullptr; cudaGetSymbolAddress((void**)&xp, g_xp);
    float* hs = nullptr; cudaGetSymbolAddress((void**)&hs, g_hs);
    float* xt = nullptr; cudaGetSymbolAddress((void**)&xt, g_xt);
    float* wt = nullptr; cudaGetSymbolAddress((void**)&wt, g_wt);

    cudaFuncSetAttribute(lstm_kernel,
                         cudaFuncAttributeMaxDynamicSharedMemorySize,
                         LSTM_SMEM_BYTES);

    dim3 gproj(G4 / 256, MM / 64);

    // ---- Layer 0 ----
    transpose_w_kernel<<<dim3(G4 / 32, DD / 32), 256>>>(Wx0, wt, DD);
    transpose_x_kernel<<<dim3(TT, DD / 32), 256>>>(x, xt);
    proj_kernel<<<gproj, 256>>>(wt, bx0, bh0, xt, DD, xp);
    reset_bar_kernel<<<1, 1>>>();
    lstm_kernel<<<128, 256, LSTM_SMEM_BYTES>>>(Wh0, xp, hs, xt);  // writes h k-major into xt

    // ---- Layer 1 ----
    transpose_w_kernel<<<dim3(G4 / 32, HH / 32), 256>>>(Wx1, wt, HH);
    proj_kernel<<<gproj, 256>>>(wt, bx1, bh1, xt, HH, xp);
    reset_bar_kernel<<<1, 1>>>();
    lstm_kernel<<<128, 256, LSTM_SMEM_BYTES>>>(Wh1, xp, hs, nullptr);

    fc_kernel<<<BB, 256>>>(fcW, fcb, out);
}

// round 4
// speedup vs baseline: 1.2426x; 1.0038x over previous
#include <cuda_runtime.h>
#include <math.h>

#define TT 1024
#define BB 32
#define DD 256
#define HH 512
#define G4 2048   // 4*H
#define OO 256
#define MM (TT * BB)
#define NCTA 128

typedef unsigned long long u64;

// ---- packed fp32x2 helpers (sm_103a FFMA2, exact fp32 numerics) ----
__device__ __forceinline__ u64 ffma2(u64 a, u64 b, u64 c) {
    u64 d; asm("fma.rn.f32x2 %0, %1, %2, %3;" : "=l"(d) : "l"(a), "l"(b), "l"(c)); return d;
}
__device__ __forceinline__ u64 dup2(float x) {
    u64 d; unsigned xi = __float_as_uint(x);
    asm("mov.b64 %0, {%1, %1};" : "=l"(d) : "r"(xi)); return d;
}
__device__ __forceinline__ float2 unpk(u64 a) {
    unsigned lo, hi; asm("mov.b64 {%0, %1}, %2;" : "=r"(lo), "=r"(hi) : "l"(a));
    return make_float2(__uint_as_float(lo), __uint_as_float(hi));
}

// Scratch (device globals: allocation-free rule)
__device__ float g_xp[(size_t)TT * G4 * BB];     // [T][4H][B] pre-activations (+ biases)
__device__ float g_q[(size_t)TT * HH * BB];      // [T][512][B] paged k-major input / h states
__device__ float g_wt[(size_t)HH * G4];          // [K][4H] k-major weights (per layer)
__device__ unsigned int g_flag[NCTA * 32];       // per-CTA epoch flags, 128B apart

__global__ void reset_flags_kernel() {
    if (threadIdx.x < NCTA) g_flag[threadIdx.x * 32] = 0u;
}

// ---------------------------------------------------------------------------
// Transpose x[B][T][D] -> q[(t*512 + d)*32 + b]. Grid (T, D/32), 256 threads.
// ---------------------------------------------------------------------------
__global__ void transpose_x_kernel(const float* __restrict__ x, float* __restrict__ q)
{
    const int t  = blockIdx.x;
    const int d0 = blockIdx.y * 32;
    const int tid = threadIdx.x;
    __shared__ float s[32][36];
    {
        int b  = tid >> 3;
        int d4 = (tid & 7) * 4;
        float4 v = *(const float4*)(x + (size_t)b * TT * DD + (size_t)t * DD + d0 + d4);
        s[b][d4 + 0] = v.x; s[b][d4 + 1] = v.y; s[b][d4 + 2] = v.z; s[b][d4 + 3] = v.w;
    }
    __syncthreads();
    {
        int d  = tid >> 3;
        int b4 = (tid & 7) * 4;
        float4 o = make_float4(s[b4 + 0][d], s[b4 + 1][d], s[b4 + 2][d], s[b4 + 3][d]);
        *(float4*)(q + ((size_t)t * HH + d0 + d) * BB + b4) = o;
    }
}

// ---------------------------------------------------------------------------
// Transpose W[2048][K] -> wt[K][2048]. Grid (2048/32, K/32), 256 threads.
// ---------------------------------------------------------------------------
__global__ void transpose_w_kernel(const float* __restrict__ W, float* __restrict__ wt, int K)
{
    const int n0 = blockIdx.x * 32;
    const int k0 = blockIdx.y * 32;
    const int tid = threadIdx.x;
    __shared__ float s[32][36];
    {
        int n  = tid >> 3;
        int k4 = (tid & 7) * 4;
        float4 v = *(const float4*)(W + (size_t)(n0 + n) * K + k0 + k4);
        s[n][k4 + 0] = v.x; s[n][k4 + 1] = v.y; s[n][k4 + 2] = v.z; s[n][k4 + 3] = v.w;
    }
    __syncthreads();
    {
        int k  = tid >> 3;
        int n4 = (tid & 7) * 4;
        float4 o = make_float4(s[n4 + 0][k], s[n4 + 1][k], s[n4 + 2][k], s[n4 + 3][k]);
        *(float4*)(wt + (size_t)(k0 + k) * G4 + n0 + n4) = o;
    }
}

// ---------------------------------------------------------------------------
// Projection GEMM: xp[t][n][b] = sum_k wt[k][n] * q[(t*512 + k)*32 + b] + bias
// Tile 256n x 64m (2 t-pages), K-tile 16, 256 thr, thread tile 8n x 8m.
// ---------------------------------------------------------------------------
__global__ void __launch_bounds__(256, 2)
proj_kernel(const float* __restrict__ wt,
            const float* __restrict__ bx,
            const float* __restrict__ bh,
            const float* __restrict__ q,
            int K,
            float* __restrict__ xp)
{
    const int n0  = blockIdx.x * 256;
    const int m0  = blockIdx.y * 64;
    const int tid = threadIdx.x;
    const int ng  = tid >> 3;
    const int mg  = tid & 7;

    __shared__ float Ws[16][264];
    __shared__ float Xs[16][72];

    u64 acc[4][8];
#pragma unroll
    for (int i = 0; i < 4; i++)
#pragma unroll
        for (int j = 0; j < 8; j++) acc[i][j] = 0ULL;

    const int xk  = tid >> 4;             // 0..15
    const int xm4 = (tid & 15) * 4;       // 0..60
    const int xt  = (m0 >> 5) + (xm4 >> 5);
    const int xb4 = xm4 & 31;

    for (int k0 = 0; k0 < K; k0 += 16) {
        __syncthreads();
#pragma unroll
        for (int i = 0; i < 4; i++) {
            int id = i * 256 + tid;
            int k  = id >> 6;
            int n4 = (id & 63) * 4;
            float4 v = *(const float4*)(wt + (size_t)(k0 + k) * G4 + n0 + n4);
            *(float4*)&Ws[k][n4] = v;
        }
        {
            float4 v = *(const float4*)(q + ((size_t)xt * HH + k0 + xk) * BB + xb4);
            *(float4*)&Xs[xk][xm4] = v;
        }
        __syncthreads();

#pragma unroll
        for (int k = 0; k < 16; k++) {
            const ulonglong2* wp = (const ulonglong2*)&Ws[k][ng * 8];
            ulonglong2 wA = wp[0];
            ulonglong2 wB = wp[1];
            float4 x0 = *(const float4*)&Xs[k][mg * 8];
            float4 x1 = *(const float4*)&Xs[k][mg * 8 + 4];
            u64 xd[8] = {dup2(x0.x), dup2(x0.y), dup2(x0.z), dup2(x0.w),
                         dup2(x1.x), dup2(x1.y), dup2(x1.z), dup2(x1.w)};
            u64 wv[4] = {wA.x, wA.y, wB.x, wB.y};
#pragma unroll
            for (int i = 0; i < 4; i++)
#pragma unroll
                for (int j = 0; j < 8; j++)
                    acc[i][j] = ffma2(wv[i], xd[j], acc[i][j]);
        }
    }

    float bias[8];
#pragma unroll
    for (int r = 0; r < 8; r++) {
        int n = n0 + ng * 8 + r;
        bias[r] = bx[n] + bh[n];
    }
    const int ot = (m0 >> 5) + (mg >> 2);
    const int ob = (mg & 3) * 8;
    float* outb = xp + ((size_t)ot * G4 + n0 + ng * 8) * BB + ob;
#pragma unroll
    for (int i = 0; i < 4; i++) {
        float2 p[8];
#pragma unroll
        for (int j = 0; j < 8; j++) p[j] = unpk(acc[i][j]);
        int rlo = 2 * i, rhi = 2 * i + 1;
        *(float4*)(outb + (size_t)rlo * BB)     = make_float4(p[0].x + bias[rlo], p[1].x + bias[rlo], p[2].x + bias[rlo], p[3].x + bias[rlo]);
        *(float4*)(outb + (size_t)rlo * BB + 4) = make_float4(p[4].x + bias[rlo], p[5].x + bias[rlo], p[6].x + bias[rlo], p[7].x + bias[rlo]);
        *(float4*)(outb + (size_t)rhi * BB)     = make_float4(p[0].y + bias[rhi], p[1].y + bias[rhi], p[2].y + bias[rhi], p[3].y + bias[rhi]);
        *(float4*)(outb + (size_t)rhi * BB + 4) = make_float4(p[4].y + bias[rhi], p[5].y + bias[rhi], p[6].y + bias[rhi], p[7].y + bias[rhi]);
    }
}

// ---------------------------------------------------------------------------
// Persistent LSTM. 128 CTAs, 256 threads. h in paged [t][k][b] layout (q).
// 8 warp-slices of 64k, split-k pipelined h load, flag-array barrier.
// SMEM: WSH 512*16 + HSH 512*32 + RED 8*16*32 + GT 16*32 + CC 128  (~114KB)
// ---------------------------------------------------------------------------
#define LSTM_SMEM_FLOATS (512*16 + 512*32 + 8*16*32 + 16*32 + 128)
#define LSTM_SMEM_BYTES  (LSTM_SMEM_FLOATS * 4)

__global__ void __launch_bounds__(256, 1)
lstm_kernel(const float* __restrict__ Wh,   // [4][H][H]
            const float* __restrict__ xp,   // [T][4H][B]
            float* __restrict__ q)          // [T][512][B]: reads h_{t-1}, writes h_t
{
    extern __shared__ float sm[];
    float* WSH = sm;                   // [k][r]  512*16
    float* HSH = WSH + 512 * 16;       // [k][b]  512*32 (no pad, conflict-free)
    float* RED = HSH + 512 * 32;       // [w][r][b] 8*16*32
    float* GT  = RED + 8 * 16 * 32;    // [r][b]
    float* CC  = GT + 16 * 32;         // [jj][b]

    const int tid  = threadIdx.x;
    const int j0   = blockIdx.x * 4;
    const int w    = tid >> 5;         // warp = k-slice owner
    const int lane = tid & 31;
    const int rg   = lane >> 3;        // 0..3  (4 rows each)
    const int bg   = lane & 7;         // 0..7  (4 b each)

    volatile unsigned int* flags = (volatile unsigned int*)g_flag;

    // Preload Wh rows transposed (one-time)
    for (int f = tid; f < 16 * 128; f += 256) {
        int r  = f >> 7;
        int c4 = (f & 127) * 4;
        int gidx = r >> 2, jj = r & 3;
        float4 v = *(const float4*)(Wh + ((size_t)gidx * HH + j0 + jj) * HH + c4);
        WSH[(c4 + 0) * 16 + r] = v.x; WSH[(c4 + 1) * 16 + r] = v.y;
        WSH[(c4 + 2) * 16 + r] = v.z; WSH[(c4 + 3) * 16 + r] = v.w;
    }
    for (int i = tid; i < 512 * 32; i += 256) HSH[i] = 0.f;
    if (tid < 128) CC[tid] = 0.f;
    __syncthreads();

    const int gr  = tid >> 3;          // xp staging row (tid<128)
    const int gb4 = (tid & 7) * 4;
    const int ggi = gr >> 2, gjj = gr & 3;
    const int sb  = tid & 31;          // state-update b (tid<128)
    const int sjj = tid >> 5;

    for (int t = 0; t < TT; t++) {
        const float* hpage = q + ((size_t)(t - 1) * HH) * BB;   // valid for t>0

        // 1) xp prefetch
        float4 xpv;
        if (tid < 128) {
            const float* src = xp + ((size_t)t * G4 + ggi * HH + j0 + gjj) * BB + gb4;
            xpv = __ldcg((const float4*)(src));
        }
        // 2) chunk0 h load (k<256): linear 32KB copy
        if (t > 0) {
            float4 hv[8];
#pragma unroll
            for (int i = 0; i < 8; i++)
                hv[i] = __ldcg((const float4*)(hpage + (size_t)(i * 256 + tid) * 4));
#pragma unroll
            for (int i = 0; i < 8; i++)
                *(float4*)&HSH[(i * 256 + tid) * 4] = hv[i];
        }
        if (tid < 128) *(float4*)&GT[gr * 32 + gb4] = xpv;
        __syncthreads();

        // 3) issue chunk1 loads, FMA chunk0 meanwhile
        float4 hv1[8];
        if (t > 0) {
#pragma unroll
            for (int i = 0; i < 8; i++)
                hv1[i] = __ldcg((const float4*)(hpage + (size_t)(8192 / 4 + i * 256 + tid) * 4));
        }

        u64 acc2[2][4];
#pragma unroll
        for (int p = 0; p < 2; p++)
#pragma unroll
            for (int j = 0; j < 4; j++) acc2[p][j] = 0ULL;

        {
            const int kbase = w * 32;
#pragma unroll 8
            for (int kk = 0; kk < 32; kk++) {
                int k = kbase + kk;
                const ulonglong2* wp2 = (const ulonglong2*)&WSH[k * 16 + rg * 4];
                ulonglong2 wv = *wp2;
                float4 h4 = *(const float4*)&HSH[k * 32 + bg * 4];
                u64 hd[4] = {dup2(h4.x), dup2(h4.y), dup2(h4.z), dup2(h4.w)};
#pragma unroll
                for (int j = 0; j < 4; j++) {
                    acc2[0][j] = ffma2(wv.x, hd[j], acc2[0][j]);
                    acc2[1][j] = ffma2(wv.y, hd[j], acc2[1][j]);
                }
            }
        }
        // 4) store chunk1 to smem, sync, FMA chunk1
        if (t > 0) {
#pragma unroll
            for (int i = 0; i < 8; i++)
                *(float4*)&HSH[8192 + (i * 256 + tid) * 4] = hv1[i];
        }
        __syncthreads();
        {
            const int kbase = 256 + w * 32;
#pragma unroll 8
            for (int kk = 0; kk < 32; kk++) {
                int k = kbase + kk;
                const ulonglong2* wp2 = (const ulonglong2*)&WSH[k * 16 + rg * 4];
                ulonglong2 wv = *wp2;
                float4 h4 = *(const float4*)&HSH[k * 32 + bg * 4];
                u64 hd[4] = {dup2(h4.x), dup2(h4.y), dup2(h4.z), dup2(h4.w)};
#pragma unroll
                for (int j = 0; j < 4; j++) {
                    acc2[0][j] = ffma2(wv.x, hd[j], acc2[0][j]);
                    acc2[1][j] = ffma2(wv.y, hd[j], acc2[1][j]);
                }
            }
        }
        // 5) write partials
#pragma unroll
        for (int p = 0; p < 2; p++) {
            float2 p0 = unpk(acc2[p][0]), p1 = unpk(acc2[p][1]);
            float2 p2 = unpk(acc2[p][2]), p3 = unpk(acc2[p][3]);
            int r0 = rg * 4 + 2 * p, r1 = r0 + 1;
            *(float4*)&RED[(w * 16 + r0) * 32 + bg * 4] = make_float4(p0.x, p1.x, p2.x, p3.x);
            *(float4*)&RED[(w * 16 + r1) * 32 + bg * 4] = make_float4(p0.y, p1.y, p2.y, p3.y);
        }
        __syncthreads();

        // 6) reduce + activations + state update + h store (coalesced line/warp)
        if (tid < 128) {
            float gv[4];
#pragma unroll
            for (int gidx = 0; gidx < 4; gidx++) {
                int r = gidx * 4 + sjj;
                float s = GT[r * 32 + sb];
#pragma unroll
                for (int ws = 0; ws < 8; ws++) s += RED[(ws * 16 + r) * 32 + sb];
                gv[gidx] = s;
            }
            float gg = tanhf(gv[0]);
            float ii = 1.f / (1.f + __expf(-gv[1]));
            float ff = 1.f / (1.f + __expf(-gv[2]));
            float oo = 1.f / (1.f + __expf(-gv[3]));
            float c  = ff * CC[sjj * 32 + sb] + ii * gg;
            CC[sjj * 32 + sb] = c;
            float h = oo * tanhf(c);
            q[((size_t)t * HH + j0 + sjj) * BB + sb] = h;
        }

        // 7) flag-array barrier: publish, then parallel-poll 128 flags
        __syncthreads();
        if (tid == 0) {
            __threadfence();
            flags[blockIdx.x * 32] = (unsigned)(t + 1);
        }
        if (tid < NCTA) {
            while (flags[tid * 32] < (unsigned)(t + 1)) { }
        }
        __syncthreads();
    }
}

// ---------------------------------------------------------------------------
// Final FC: out[b][o] = sum_k q[T-1][k][b] * fcW[o][k] + fcb[o]
// ---------------------------------------------------------------------------
__global__ void fc_kernel(const float* __restrict__ fcW,
                          const float* __restrict__ fcb,
                          float* __restrict__ out)
{
    const int b = blockIdx.x;
    const int o = threadIdx.x;
    __shared__ float hsh[HH];
    for (int k = threadIdx.x; k < HH; k += blockDim.x)
        hsh[k] = g_q[((size_t)(TT - 1) * HH + k) * BB + b];
    __syncthreads();
    float acc = 0.f;
    const float* wv = fcW + (size_t)o * HH;
#pragma unroll 8
    for (int k = 0; k < HH; k += 4) {
        float4 w4 = *(const float4*)(wv + k);
        acc += w4.x * hsh[k] + w4.y * hsh[k + 1] + w4.z * hsh[k + 2] + w4.w * hsh[k + 3];
    }
    out[(size_t)b * OO + o] = acc + fcb[o];
}

// ---------------------------------------------------------------------------
extern "C" void kernel_launch(void* const* d_in, const int* in_sizes, int n_in,
                              void* d_out, int out_size)
{
    const float* x   = (const float*)d_in[0];
    const float* Wx0 = (const float*)d_in[1];
    const float* bx0 = (const float*)d_in[2];
    const float* Wh0 = (const float*)d_in[3];
    const float* bh0 = (const float*)d_in[4];
    const float* Wx1 = (const float*)d_in[5];
    const float* bx1 = (const float*)d_in[6];
    const float* Wh1 = (const float*)d_in[7];
    const float* bh1 = (const float*)d_in[8];
    const float* fcW = (const float*)d_in[9];
    const float* fcb = (const float*)d_in[10];
    float* out = (float*)d_out;
    (void)in_sizes; (void)n_in; (void)out_size;

    float* xp = nullptr; cudaGetSymbolAddress((void**)&xp, g_xp);
    float* q  = nullptr; cudaGetSymbolAddress((void**)&q,  g_q);
    float* wt = nullptr; cudaGetSymbolAddress((void**)&wt, g_wt);

    cudaFuncSetAttribute(lstm_kernel,
                         cudaFuncAttributeMaxDynamicSharedMemorySize,
                         LSTM_SMEM_BYTES);

    dim3 gproj(G4 / 256, MM / 64);

    // ---- Layer 0 ----
    transpose_w_kernel<<<dim3(G4 / 32, DD / 32), 256>>>(Wx0, wt, DD);
    transpose_x_kernel<<<dim3(TT, DD / 32), 256>>>(x, q);
    proj_kernel<<<gproj, 256>>>(wt, bx0, bh0, q, DD, xp);
    reset_flags_kernel<<<1, 128>>>();
    lstm_kernel<<<NCTA, 256, LSTM_SMEM_BYTES>>>(Wh0, xp, q);  // overwrites q pages with h

    // ---- Layer 1 ----
    transpose_w_kernel<<<dim3(G4 / 32, HH / 32), 256>>>(Wx1, wt, HH);
    proj_kernel<<<gproj, 256>>>(wt, bx1, bh1, q, HH, xp);
    reset_flags_kernel<<<1, 128>>>();
    lstm_kernel<<<NCTA, 256, LSTM_SMEM_BYTES>>>(Wh1, xp, q);

    fc_kernel<<<BB, 256>>>(fcW, fcb, out);
}

// round 5
// speedup vs baseline: 1.3131x; 1.0568x over previous
#include <cuda_runtime.h>
#include <math.h>

#define TT 1024
#define BB 32
#define DD 256
#define HH 512
#define G4 2048   // 4*H
#define OO 256
#define MM (TT * BB)
#define NCTA 128

typedef unsigned long long u64;

// ---- packed fp32x2 helpers (sm_103a FFMA2, exact fp32 numerics) ----
__device__ __forceinline__ u64 ffma2(u64 a, u64 b, u64 c) {
    u64 d; asm("fma.rn.f32x2 %0, %1, %2, %3;" : "=l"(d) : "l"(a), "l"(b), "l"(c)); return d;
}
__device__ __forceinline__ u64 dup2(float x) {
    u64 d; unsigned xi = __float_as_uint(x);
    asm("mov.b64 %0, {%1, %1};" : "=l"(d) : "r"(xi)); return d;
}
__device__ __forceinline__ float2 unpk(u64 a) {
    unsigned lo, hi; asm("mov.b64 {%0, %1}, %2;" : "=r"(lo), "=r"(hi) : "l"(a));
    return make_float2(__uint_as_float(lo), __uint_as_float(hi));
}
__device__ __forceinline__ float fsig(float y) {          // sigmoid via MUFU
    return __fdividef(1.f, 1.f + __expf(-y));
}
__device__ __forceinline__ float ftanh(float x) {         // tanh = 2*sig(2x)-1
    return 2.f * fsig(2.f * x) - 1.f;
}

// Scratch (device globals: allocation-free rule)
__device__ float g_xp[(size_t)TT * G4 * BB];     // [T][4H][B] pre-activations (+ biases)
__device__ float g_q[(size_t)TT * HH * BB];      // [T][512][B] paged k-major input / h states
__device__ float g_wt[(size_t)HH * G4];          // [K][4H] k-major weights (per layer)
__device__ unsigned int g_flag[NCTA * 32];       // per-CTA epoch flags, 128B apart

// ---------------------------------------------------------------------------
// Transpose x[B][T][D] -> q[(t*512 + d)*32 + b]; block(0,0) also zeroes flags.
// ---------------------------------------------------------------------------
__global__ void transpose_x_kernel(const float* __restrict__ x, float* __restrict__ q)
{
    const int t  = blockIdx.x;
    const int d0 = blockIdx.y * 32;
    const int tid = threadIdx.x;
    if (blockIdx.x == 0 && blockIdx.y == 0 && tid < NCTA) g_flag[tid * 32] = 0u;
    __shared__ float s[32][36];
    {
        int b  = tid >> 3;
        int d4 = (tid & 7) * 4;
        float4 v = *(const float4*)(x + (size_t)b * TT * DD + (size_t)t * DD + d0 + d4);
        s[b][d4 + 0] = v.x; s[b][d4 + 1] = v.y; s[b][d4 + 2] = v.z; s[b][d4 + 3] = v.w;
    }
    __syncthreads();
    {
        int d  = tid >> 3;
        int b4 = (tid & 7) * 4;
        float4 o = make_float4(s[b4 + 0][d], s[b4 + 1][d], s[b4 + 2][d], s[b4 + 3][d]);
        *(float4*)(q + ((size_t)t * HH + d0 + d) * BB + b4) = o;
    }
}

// ---------------------------------------------------------------------------
// Transpose W[2048][K] -> wt[K][2048]. Grid (2048/32, K/32), 256 threads.
// ---------------------------------------------------------------------------
__global__ void transpose_w_kernel(const float* __restrict__ W, float* __restrict__ wt, int K)
{
    const int n0 = blockIdx.x * 32;
    const int k0 = blockIdx.y * 32;
    const int tid = threadIdx.x;
    __shared__ float s[32][36];
    {
        int n  = tid >> 3;
        int k4 = (tid & 7) * 4;
        float4 v = *(const float4*)(W + (size_t)(n0 + n) * K + k0 + k4);
        s[n][k4 + 0] = v.x; s[n][k4 + 1] = v.y; s[n][k4 + 2] = v.z; s[n][k4 + 3] = v.w;
    }
    __syncthreads();
    {
        int k  = tid >> 3;
        int n4 = (tid & 7) * 4;
        float4 o = make_float4(s[n4 + 0][k], s[n4 + 1][k], s[n4 + 2][k], s[n4 + 3][k]);
        *(float4*)(wt + (size_t)(k0 + k) * G4 + n0 + n4) = o;
    }
}

// ---------------------------------------------------------------------------
// Projection GEMM: xp[t][n][b] = sum_k wt[k][n] * q[(t*512 + k)*32 + b] + bias
// Tile 256n x 64m (2 t-pages), K-tile 16, 256 thr, thread tile 8n x 8m.
// ---------------------------------------------------------------------------
__global__ void __launch_bounds__(256, 2)
proj_kernel(const float* __restrict__ wt,
            const float* __restrict__ bx,
            const float* __restrict__ bh,
            const float* __restrict__ q,
            int K,
            float* __restrict__ xp)
{
    const int n0  = blockIdx.x * 256;
    const int m0  = blockIdx.y * 64;
    const int tid = threadIdx.x;
    const int ng  = tid >> 3;
    const int mg  = tid & 7;

    __shared__ float Ws[16][264];
    __shared__ float Xs[16][72];

    u64 acc[4][8];
#pragma unroll
    for (int i = 0; i < 4; i++)
#pragma unroll
        for (int j = 0; j < 8; j++) acc[i][j] = 0ULL;

    const int xk  = tid >> 4;
    const int xm4 = (tid & 15) * 4;
    const int xt  = (m0 >> 5) + (xm4 >> 5);
    const int xb4 = xm4 & 31;

    for (int k0 = 0; k0 < K; k0 += 16) {
        __syncthreads();
#pragma unroll
        for (int i = 0; i < 4; i++) {
            int id = i * 256 + tid;
            int k  = id >> 6;
            int n4 = (id & 63) * 4;
            float4 v = *(const float4*)(wt + (size_t)(k0 + k) * G4 + n0 + n4);
            *(float4*)&Ws[k][n4] = v;
        }
        {
            float4 v = *(const float4*)(q + ((size_t)xt * HH + k0 + xk) * BB + xb4);
            *(float4*)&Xs[xk][xm4] = v;
        }
        __syncthreads();

#pragma unroll
        for (int k = 0; k < 16; k++) {
            const ulonglong2* wp = (const ulonglong2*)&Ws[k][ng * 8];
            ulonglong2 wA = wp[0];
            ulonglong2 wB = wp[1];
            float4 x0 = *(const float4*)&Xs[k][mg * 8];
            float4 x1 = *(const float4*)&Xs[k][mg * 8 + 4];
            u64 xd[8] = {dup2(x0.x), dup2(x0.y), dup2(x0.z), dup2(x0.w),
                         dup2(x1.x), dup2(x1.y), dup2(x1.z), dup2(x1.w)};
            u64 wv[4] = {wA.x, wA.y, wB.x, wB.y};
#pragma unroll
            for (int i = 0; i < 4; i++)
#pragma unroll
                for (int j = 0; j < 8; j++)
                    acc[i][j] = ffma2(wv[i], xd[j], acc[i][j]);
        }
    }

    float bias[8];
#pragma unroll
    for (int r = 0; r < 8; r++) {
        int n = n0 + ng * 8 + r;
        bias[r] = bx[n] + bh[n];
    }
    const int ot = (m0 >> 5) + (mg >> 2);
    const int ob = (mg & 3) * 8;
    float* outb = xp + ((size_t)ot * G4 + n0 + ng * 8) * BB + ob;
#pragma unroll
    for (int i = 0; i < 4; i++) {
        float2 p[8];
#pragma unroll
        for (int j = 0; j < 8; j++) p[j] = unpk(acc[i][j]);
        int rlo = 2 * i, rhi = 2 * i + 1;
        *(float4*)(outb + (size_t)rlo * BB)     = make_float4(p[0].x + bias[rlo], p[1].x + bias[rlo], p[2].x + bias[rlo], p[3].x + bias[rlo]);
        *(float4*)(outb + (size_t)rlo * BB + 4) = make_float4(p[4].x + bias[rlo], p[5].x + bias[rlo], p[6].x + bias[rlo], p[7].x + bias[rlo]);
        *(float4*)(outb + (size_t)rhi * BB)     = make_float4(p[0].y + bias[rhi], p[1].y + bias[rhi], p[2].y + bias[rhi], p[3].y + bias[rhi]);
        *(float4*)(outb + (size_t)rhi * BB + 4) = make_float4(p[4].y + bias[rhi], p[5].y + bias[rhi], p[6].y + bias[rhi], p[7].y + bias[rhi]);
    }
}

// ---------------------------------------------------------------------------
// Persistent LSTM. 128 CTAs, 256 threads. h in paged [t][k][b] layout (q).
// Epoch-monotonic flag barrier (ebase = layer*TT); xp prefetched under barrier.
// ---------------------------------------------------------------------------
#define LSTM_SMEM_FLOATS (512*16 + 512*32 + 8*16*32 + 16*32 + 128)
#define LSTM_SMEM_BYTES  (LSTM_SMEM_FLOATS * 4)

__global__ void __launch_bounds__(256, 1)
lstm_kernel(const float* __restrict__ Wh,   // [4][H][H]
            const float* __restrict__ xp,   // [T][4H][B]
            float* __restrict__ q,          // [T][512][B]: reads h_{t-1}, writes h_t
            unsigned int ebase)             // flag epoch base (layer*TT)
{
    extern __shared__ float sm[];
    float* WSH = sm;                   // [k][r]  512*16
    float* HSH = WSH + 512 * 16;       // [k][b]  512*32
    float* RED = HSH + 512 * 32;       // [w][r][b] 8*16*32
    float* GT  = RED + 8 * 16 * 32;    // [r][b]
    float* CC  = GT + 16 * 32;         // [jj][b]

    const int tid  = threadIdx.x;
    const int j0   = blockIdx.x * 4;
    const int w    = tid >> 5;
    const int lane = tid & 31;
    const int rg   = lane >> 3;
    const int bg   = lane & 7;

    volatile unsigned int* flags = (volatile unsigned int*)g_flag;

    for (int f = tid; f < 16 * 128; f += 256) {
        int r  = f >> 7;
        int c4 = (f & 127) * 4;
        int gidx = r >> 2, jj = r & 3;
        float4 v = *(const float4*)(Wh + ((size_t)gidx * HH + j0 + jj) * HH + c4);
        WSH[(c4 + 0) * 16 + r] = v.x; WSH[(c4 + 1) * 16 + r] = v.y;
        WSH[(c4 + 2) * 16 + r] = v.z; WSH[(c4 + 3) * 16 + r] = v.w;
    }
    for (int i = tid; i < 512 * 32; i += 256) HSH[i] = 0.f;
    if (tid < 128) CC[tid] = 0.f;
    __syncthreads();

    const int gr  = tid >> 3;
    const int gb4 = (tid & 7) * 4;
    const int ggi = gr >> 2, gjj = gr & 3;
    const int sb  = tid & 31;
    const int sjj = tid >> 5;
    const float* xpsrc = xp + ((size_t)ggi * HH + j0 + gjj) * BB + gb4;

    // Prologue prefetch of xp[0]
    float4 xpv;
    if (tid < 128) xpv = __ldcg((const float4*)xpsrc);

    for (int t = 0; t < TT; t++) {
        const float* hpage = q + ((size_t)(t - 1) * HH) * BB;   // valid for t>0

        // 1) h chunk0 (k<256): linear 32KB copy
        if (t > 0) {
            float4 hv[8];
#pragma unroll
            for (int i = 0; i < 8; i++)
                hv[i] = __ldcg((const float4*)(hpage + (size_t)(i * 256 + tid) * 4));
#pragma unroll
            for (int i = 0; i < 8; i++)
                *(float4*)&HSH[(i * 256 + tid) * 4] = hv[i];
        }
        if (tid < 128) *(float4*)&GT[gr * 32 + gb4] = xpv;
        __syncthreads();

        // 2) issue chunk1 loads; FMA chunk0 meanwhile
        float4 hv1[8];
        if (t > 0) {
#pragma unroll
            for (int i = 0; i < 8; i++)
                hv1[i] = __ldcg((const float4*)(hpage + (size_t)(2048 + i * 256 + tid) * 4));
        }

        u64 acc2[2][4];
#pragma unroll
        for (int p = 0; p < 2; p++)
#pragma unroll
            for (int j = 0; j < 4; j++) acc2[p][j] = 0ULL;

        {
            const int kbase = w * 32;
#pragma unroll 8
            for (int kk = 0; kk < 32; kk++) {
                int k = kbase + kk;
                ulonglong2 wv = *(const ulonglong2*)&WSH[k * 16 + rg * 4];
                float4 h4 = *(const float4*)&HSH[k * 32 + bg * 4];
                u64 hd[4] = {dup2(h4.x), dup2(h4.y), dup2(h4.z), dup2(h4.w)};
#pragma unroll
                for (int j = 0; j < 4; j++) {
                    acc2[0][j] = ffma2(wv.x, hd[j], acc2[0][j]);
                    acc2[1][j] = ffma2(wv.y, hd[j], acc2[1][j]);
                }
            }
        }
        if (t > 0) {
#pragma unroll
            for (int i = 0; i < 8; i++)
                *(float4*)&HSH[8192 + (i * 256 + tid) * 4] = hv1[i];
        }
        __syncthreads();
        {
            const int kbase = 256 + w * 32;
#pragma unroll 8
            for (int kk = 0; kk < 32; kk++) {
                int k = kbase + kk;
                ulonglong2 wv = *(const ulonglong2*)&WSH[k * 16 + rg * 4];
                float4 h4 = *(const float4*)&HSH[k * 32 + bg * 4];
                u64 hd[4] = {dup2(h4.x), dup2(h4.y), dup2(h4.z), dup2(h4.w)};
#pragma unroll
                for (int j = 0; j < 4; j++) {
                    acc2[0][j] = ffma2(wv.x, hd[j], acc2[0][j]);
                    acc2[1][j] = ffma2(wv.y, hd[j], acc2[1][j]);
                }
            }
        }
#pragma unroll
        for (int p = 0; p < 2; p++) {
            float2 p0 = unpk(acc2[p][0]), p1 = unpk(acc2[p][1]);
            float2 p2 = unpk(acc2[p][2]), p3 = unpk(acc2[p][3]);
            int r0 = rg * 4 + 2 * p, r1 = r0 + 1;
            *(float4*)&RED[(w * 16 + r0) * 32 + bg * 4] = make_float4(p0.x, p1.x, p2.x, p3.x);
            *(float4*)&RED[(w * 16 + r1) * 32 + bg * 4] = make_float4(p0.y, p1.y, p2.y, p3.y);
        }
        __syncthreads();

        // 3) reduce + activations (MUFU-based) + state update + h store
        if (tid < 128) {
            float gv[4];
#pragma unroll
            for (int gidx = 0; gidx < 4; gidx++) {
                int r = gidx * 4 + sjj;
                float s = GT[r * 32 + sb];
#pragma unroll
                for (int ws = 0; ws < 8; ws++) s += RED[(ws * 16 + r) * 32 + sb];
                gv[gidx] = s;
            }
            float gg = ftanh(gv[0]);
            float ii = fsig(gv[1]);
            float ff = fsig(gv[2]);
            float oo = fsig(gv[3]);
            float c  = ff * CC[sjj * 32 + sb] + ii * gg;
            CC[sjj * 32 + sb] = c;
            float h = oo * ftanh(c);
            q[((size_t)t * HH + j0 + sjj) * BB + sb] = h;
        }

        // 4) publish, prefetch next xp under the wait, poll, sync
        __syncthreads();
        if (tid == 0) {
            __threadfence();
            flags[blockIdx.x * 32] = ebase + (unsigned)(t + 1);
        }
        if (tid < 128 && t + 1 < TT)
            xpv = __ldcg((const float4*)(xpsrc + (size_t)(t + 1) * G4 * BB));
        if (tid < NCTA) {
            unsigned want = ebase + (unsigned)(t + 1);
            while (flags[tid * 32] < want) { }
        }
        __syncthreads();
    }
}

// ---------------------------------------------------------------------------
// Final FC: out[b][o] = sum_k q[T-1][k][b] * fcW[o][k] + fcb[o]
// ---------------------------------------------------------------------------
__global__ void fc_kernel(const float* __restrict__ fcW,
                          const float* __restrict__ fcb,
                          float* __restrict__ out)
{
    const int b = blockIdx.x;
    const int o = threadIdx.x;
    __shared__ float hsh[HH];
    for (int k = threadIdx.x; k < HH; k += blockDim.x)
        hsh[k] = g_q[((size_t)(TT - 1) * HH + k) * BB + b];
    __syncthreads();
    float acc = 0.f;
    const float* wv = fcW + (size_t)o * HH;
#pragma unroll 8
    for (int k = 0; k < HH; k += 4) {
        float4 w4 = *(const float4*)(wv + k);
        acc += w4.x * hsh[k] + w4.y * hsh[k + 1] + w4.z * hsh[k + 2] + w4.w * hsh[k + 3];
    }
    out[(size_t)b * OO + o] = acc + fcb[o];
}

// ---------------------------------------------------------------------------
extern "C" void kernel_launch(void* const* d_in, const int* in_sizes, int n_in,
                              void* d_out, int out_size)
{
    const float* x   = (const float*)d_in[0];
    const float* Wx0 = (const float*)d_in[1];
    const float* bx0 = (const float*)d_in[2];
    const float* Wh0 = (const float*)d_in[3];
    const float* bh0 = (const float*)d_in[4];
    const float* Wx1 = (const float*)d_in[5];
    const float* bx1 = (const float*)d_in[6];
    const float* Wh1 = (const float*)d_in[7];
    const float* bh1 = (const float*)d_in[8];
    const float* fcW = (const float*)d_in[9];
    const float* fcb = (const float*)d_in[10];
    float* out = (float*)d_out;
    (void)in_sizes; (void)n_in; (void)out_size;

    float* xp = nullptr; cudaGetSymbolAddress((void**)&xp, g_xp);
    float* q  = nullptr; cudaGetSymbolAddress((void**)&q,  g_q);
    float* wt = nullptr; cudaGetSymbolAddress((void**)&wt, g_wt);

    cudaFuncSetAttribute(lstm_kernel,
                         cudaFuncAttributeMaxDynamicSharedMemorySize,
                         LSTM_SMEM_BYTES);

    dim3 gproj(G4 / 256, MM / 64);

    // ---- Layer 0 ----  (launch order puts lstm0 at index 3 for ncu capture)
    transpose_w_kernel<<<dim3(G4 / 32, DD / 32), 256>>>(Wx0, wt, DD);      // 0
    transpose_x_kernel<<<dim3(TT, DD / 32), 256>>>(x, q);                  // 1 (+flag reset)
    proj_kernel<<<gproj, 256>>>(wt, bx0, bh0, q, DD, xp);                  // 2
    lstm_kernel<<<NCTA, 256, LSTM_SMEM_BYTES>>>(Wh0, xp, q, 0u);           // 3

    // ---- Layer 1 ----
    transpose_w_kernel<<<dim3(G4 / 32, HH / 32), 256>>>(Wx1, wt, HH);      // 4
    proj_kernel<<<gproj, 256>>>(wt, bx1, bh1, q, HH, xp);                  // 5
    lstm_kernel<<<NCTA, 256, LSTM_SMEM_BYTES>>>(Wh1, xp, q, (unsigned)TT); // 6

    fc_kernel<<<BB, 256>>>(fcW, fcb, out);                                 // 7
}

// round 6
// speedup vs baseline: 1.5982x; 1.2171x over previous
#include <cuda_runtime.h>
#include <math.h>

#define TT 1024
#define BB 32
#define DD 256
#define HH 512
#define G4 2048   // 4*H
#define OO 256
#define MM (TT * BB)
#define NCTA 128
#define NGRP 4
#define GSZ  32     // CTAs per group
#define GB   8      // batch per group

typedef unsigned long long u64;

// ---- packed fp32x2 helpers (sm_103a FFMA2, exact fp32 numerics) ----
__device__ __forceinline__ u64 ffma2(u64 a, u64 b, u64 c) {
    u64 d; asm("fma.rn.f32x2 %0, %1, %2, %3;" : "=l"(d) : "l"(a), "l"(b), "l"(c)); return d;
}
__device__ __forceinline__ u64 dup2(float x) {
    u64 d; unsigned xi = __float_as_uint(x);
    asm("mov.b64 %0, {%1, %1};" : "=l"(d) : "r"(xi)); return d;
}
__device__ __forceinline__ float2 unpk(u64 a) {
    unsigned lo, hi; asm("mov.b64 {%0, %1}, %2;" : "=r"(lo), "=r"(hi) : "l"(a));
    return make_float2(__uint_as_float(lo), __uint_as_float(hi));
}
__device__ __forceinline__ float fsig(float y) { return __fdividef(1.f, 1.f + __expf(-y)); }
__device__ __forceinline__ float ftanh(float x) { return 2.f * fsig(2.f * x) - 1.f; }

// Scratch (device globals: allocation-free rule)
__device__ float g_xp[(size_t)TT * G4 * BB];          // [T][4H][B] pre-activations (+ biases)
__device__ float g_h[(size_t)NGRP * TT * HH * GB];    // [g][t][k][8] group-local k-major data
__device__ float g_wt[(size_t)HH * G4];               // [K][4H] k-major weights (per layer)
__device__ unsigned int g_flag[NCTA * 32];            // per-CTA epoch flags, 128B apart

// ---------------------------------------------------------------------------
// Transpose x[B][T][D] -> g_h[(g*T + t)*D + d][8] ; block(0,0) zeroes flags.
// ---------------------------------------------------------------------------
__global__ void transpose_x_kernel(const float* __restrict__ x, float* __restrict__ gh)
{
    const int t  = blockIdx.x;
    const int d0 = blockIdx.y * 32;
    const int tid = threadIdx.x;
    if (blockIdx.x == 0 && blockIdx.y == 0 && tid < NCTA) g_flag[tid * 32] = 0u;
    __shared__ float s[32][36];
    {
        int b  = tid >> 3;
        int d4 = (tid & 7) * 4;
        float4 v = *(const float4*)(x + (size_t)b * TT * DD + (size_t)t * DD + d0 + d4);
        s[b][d4 + 0] = v.x; s[b][d4 + 1] = v.y; s[b][d4 + 2] = v.z; s[b][d4 + 3] = v.w;
    }
    __syncthreads();
    {
        int d  = tid >> 3;
        int b4 = (tid & 7) * 4;        // 0,4,...,28
        int g  = b4 >> 3;
        int off= b4 & 7;               // 0 or 4
        float4 o = make_float4(s[b4 + 0][d], s[b4 + 1][d], s[b4 + 2][d], s[b4 + 3][d]);
        *(float4*)(gh + (((size_t)g * TT + t) * DD + d0 + d) * GB + off) = o;
    }
}

// ---------------------------------------------------------------------------
// Transpose W[2048][K] -> wt[K][2048].
// ---------------------------------------------------------------------------
__global__ void transpose_w_kernel(const float* __restrict__ W, float* __restrict__ wt, int K)
{
    const int n0 = blockIdx.x * 32;
    const int k0 = blockIdx.y * 32;
    const int tid = threadIdx.x;
    __shared__ float s[32][36];
    {
        int n  = tid >> 3;
        int k4 = (tid & 7) * 4;
        float4 v = *(const float4*)(W + (size_t)(n0 + n) * K + k0 + k4);
        s[n][k4 + 0] = v.x; s[n][k4 + 1] = v.y; s[n][k4 + 2] = v.z; s[n][k4 + 3] = v.w;
    }
    __syncthreads();
    {
        int k  = tid >> 3;
        int n4 = (tid & 7) * 4;
        float4 o = make_float4(s[n4 + 0][k], s[n4 + 1][k], s[n4 + 2][k], s[n4 + 3][k]);
        *(float4*)(wt + (size_t)(k0 + k) * G4 + n0 + n4) = o;
    }
}

// ---------------------------------------------------------------------------
// Projection GEMM: xp[t][n][b] = sum_k wt[k][n] * gh[(g*T+t)*K + k][b&7] + bias
// Tile 256n x 64m, K-tile 16, 256 thr, thread tile 8n x 8m.
// ---------------------------------------------------------------------------
__global__ void __launch_bounds__(256, 2)
proj_kernel(const float* __restrict__ wt,
            const float* __restrict__ bx,
            const float* __restrict__ bh,
            const float* __restrict__ gh,
            int K,
            float* __restrict__ xp)
{
    const int n0  = blockIdx.x * 256;
    const int m0  = blockIdx.y * 64;
    const int tid = threadIdx.x;
    const int ng  = tid >> 3;
    const int mg  = tid & 7;

    __shared__ float Ws[16][264];
    __shared__ float Xs[16][72];

    u64 acc[4][8];
#pragma unroll
    for (int i = 0; i < 4; i++)
#pragma unroll
        for (int j = 0; j < 8; j++) acc[i][j] = 0ULL;

    const int xk  = tid >> 4;             // 0..15
    const int xm4 = (tid & 15) * 4;       // 0..60
    const int xt  = (m0 >> 5) + (xm4 >> 5);
    const int xb4 = xm4 & 31;
    const int xg  = xb4 >> 3;
    const int xoff= xb4 & 7;
    const float* xsrc = gh + (((size_t)xg * TT + xt) * K) * GB + xoff;

    for (int k0 = 0; k0 < K; k0 += 16) {
        __syncthreads();
#pragma unroll
        for (int i = 0; i < 4; i++) {
            int id = i * 256 + tid;
            int k  = id >> 6;
            int n4 = (id & 63) * 4;
            float4 v = *(const float4*)(wt + (size_t)(k0 + k) * G4 + n0 + n4);
            *(float4*)&Ws[k][n4] = v;
        }
        {
            float4 v = *(const float4*)(xsrc + (size_t)(k0 + xk) * GB);
            *(float4*)&Xs[xk][xm4] = v;
        }
        __syncthreads();

#pragma unroll
        for (int k = 0; k < 16; k++) {
            const ulonglong2* wp = (const ulonglong2*)&Ws[k][ng * 8];
            ulonglong2 wA = wp[0];
            ulonglong2 wB = wp[1];
            float4 x0 = *(const float4*)&Xs[k][mg * 8];
            float4 x1 = *(const float4*)&Xs[k][mg * 8 + 4];
            u64 xd[8] = {dup2(x0.x), dup2(x0.y), dup2(x0.z), dup2(x0.w),
                         dup2(x1.x), dup2(x1.y), dup2(x1.z), dup2(x1.w)};
            u64 wv[4] = {wA.x, wA.y, wB.x, wB.y};
#pragma unroll
            for (int i = 0; i < 4; i++)
#pragma unroll
                for (int j = 0; j < 8; j++)
                    acc[i][j] = ffma2(wv[i], xd[j], acc[i][j]);
        }
    }

    float bias[8];
#pragma unroll
    for (int r = 0; r < 8; r++) {
        int n = n0 + ng * 8 + r;
        bias[r] = bx[n] + bh[n];
    }
    const int ot = (m0 >> 5) + (mg >> 2);
    const int ob = (mg & 3) * 8;
    float* outb = xp + ((size_t)ot * G4 + n0 + ng * 8) * BB + ob;
#pragma unroll
    for (int i = 0; i < 4; i++) {
        float2 p[8];
#pragma unroll
        for (int j = 0; j < 8; j++) p[j] = unpk(acc[i][j]);
        int rlo = 2 * i, rhi = 2 * i + 1;
        *(float4*)(outb + (size_t)rlo * BB)     = make_float4(p[0].x + bias[rlo], p[1].x + bias[rlo], p[2].x + bias[rlo], p[3].x + bias[rlo]);
        *(float4*)(outb + (size_t)rlo * BB + 4) = make_float4(p[4].x + bias[rlo], p[5].x + bias[rlo], p[6].x + bias[rlo], p[7].x + bias[rlo]);
        *(float4*)(outb + (size_t)rhi * BB)     = make_float4(p[0].y + bias[rhi], p[1].y + bias[rhi], p[2].y + bias[rhi], p[3].y + bias[rhi]);
        *(float4*)(outb + (size_t)rhi * BB + 4) = make_float4(p[4].y + bias[rhi], p[5].y + bias[rhi], p[6].y + bias[rhi], p[7].y + bias[rhi]);
    }
}

// ---------------------------------------------------------------------------
// Persistent LSTM. 4 independent groups x 32 CTAs; CTA owns 16 j x 8 batch.
// Wh slice (64 rows x 512) resident in smem; h in group-local [t][k][8] layout.
// SMEM: WSH 512*64 + HSH 512*8 + RED 8*64*8 + GT 64*8 + CC 16*8  (~163KB)
// ---------------------------------------------------------------------------
#define LSTM_SMEM_FLOATS (512*64 + 512*8 + 8*64*8 + 64*8 + 16*8)
#define LSTM_SMEM_BYTES  (LSTM_SMEM_FLOATS * 4)

__global__ void __launch_bounds__(256, 1)
lstm_kernel(const float* __restrict__ Wh,   // [4][H][H]
            const float* __restrict__ xp,   // [T][4H][B]
            float* __restrict__ gh,         // [g][T][512][8]: reads h_{t-1}, writes h_t
            unsigned int ebase)             // flag epoch base (layer*TT)
{
    extern __shared__ float sm[];
    float* WSH = sm;                    // [k][64 rows]
    float* HSH = WSH + 512 * 64;        // [k][8]
    float* RED = HSH + 512 * 8;         // [w][64 rows][8]
    float* GT  = RED + 8 * 64 * 8;      // [64 rows][8]
    float* CC  = GT + 64 * 8;           // [16 j][8]

    const int tid   = threadIdx.x;
    const int rank  = blockIdx.x & 31;
    const int group = blockIdx.x >> 5;
    const int j0    = rank * 16;        // 16 hidden units per CTA
    const int gb0   = group * GB;       // batch base
    const int w     = tid >> 5;         // warp = k-slice of 64
    const int lane  = tid & 31;
    const int rgr   = lane >> 1;        // 0..15 -> rows rgr*4..+3
    const int bgr   = lane & 1;         // 0..1  -> b bgr*4..+3

    volatile unsigned int* flags = (volatile unsigned int*)g_flag;

    // Preload Wh slice transposed: rows r = gate*16 + jl
    for (int f = tid; f < 64 * 128; f += 256) {
        int r  = f >> 7;
        int c4 = (f & 127) * 4;
        int gate = r >> 4, jl = r & 15;
        float4 v = *(const float4*)(Wh + ((size_t)gate * HH + j0 + jl) * HH + c4);
        WSH[(c4 + 0) * 64 + r] = v.x; WSH[(c4 + 1) * 64 + r] = v.y;
        WSH[(c4 + 2) * 64 + r] = v.z; WSH[(c4 + 3) * 64 + r] = v.w;
    }
    for (int i = tid; i < 512 * 8; i += 256) HSH[i] = 0.f;
    if (tid < 128) CC[tid] = 0.f;
    __syncthreads();

    // Per-thread fixed indices
    const int gr   = tid >> 1;          // GT row (tid<128)
    const int ghalf= tid & 1;
    const int ggate= gr >> 4, gjl = gr & 15;
    const float* xpsrc = xp + ((size_t)ggate * HH + j0 + gjl) * BB + gb0 + ghalf * 4;
    const int sjl  = tid >> 3;          // state j (tid<128)
    const int sbb  = tid & 7;

    float* ghg = gh + (size_t)group * TT * HH * GB;

    // Prologue prefetch of xp[0]
    float4 xpv;
    if (tid < 128) xpv = __ldcg((const float4*)xpsrc);

    for (int t = 0; t < TT; t++) {
        // 1) load h_{t-1} (16KB linear) + stage GT
        if (t > 0) {
            const float* hb = ghg + (size_t)(t - 1) * HH * GB;
            float4 hv[4];
#pragma unroll
            for (int i = 0; i < 4; i++)
                hv[i] = __ldcg((const float4*)(hb + (size_t)(i * 256 + tid) * 4));
#pragma unroll
            for (int i = 0; i < 4; i++)
                *(float4*)&HSH[(i * 256 + tid) * 4] = hv[i];
        }
        if (tid < 128) *(float4*)&GT[gr * GB + ghalf * 4] = xpv;
        __syncthreads();

        // 2) FFMA2 partial GEMM: 4 rows x 4 b per thread over a 64-wide k slice
        u64 acc2[2][4];
#pragma unroll
        for (int p = 0; p < 2; p++)
#pragma unroll
            for (int j = 0; j < 4; j++) acc2[p][j] = 0ULL;

        const int kbase = w * 64;
        const int r0 = rgr * 4;
        const int b0 = bgr * 4;
#pragma unroll 8
        for (int kk = 0; kk < 64; kk++) {
            int k = kbase + kk;
            ulonglong2 wv = *(const ulonglong2*)&WSH[k * 64 + r0];
            float4 h4 = *(const float4*)&HSH[k * GB + b0];
            u64 hd[4] = {dup2(h4.x), dup2(h4.y), dup2(h4.z), dup2(h4.w)};
#pragma unroll
            for (int j = 0; j < 4; j++) {
                acc2[0][j] = ffma2(wv.x, hd[j], acc2[0][j]);
                acc2[1][j] = ffma2(wv.y, hd[j], acc2[1][j]);
            }
        }
#pragma unroll
        for (int p = 0; p < 2; p++) {
            float2 p0 = unpk(acc2[p][0]), p1 = unpk(acc2[p][1]);
            float2 p2 = unpk(acc2[p][2]), p3 = unpk(acc2[p][3]);
            int rr0 = r0 + 2 * p, rr1 = rr0 + 1;
            *(float4*)&RED[(w * 64 + rr0) * GB + b0] = make_float4(p0.x, p1.x, p2.x, p3.x);
            *(float4*)&RED[(w * 64 + rr1) * GB + b0] = make_float4(p0.y, p1.y, p2.y, p3.y);
        }
        __syncthreads();

        // 3) reduce + activations + state update + h store
        if (tid < 128) {
            float gv[4];
#pragma unroll
            for (int gate = 0; gate < 4; gate++) {
                int r = gate * 16 + sjl;
                float s = GT[r * GB + sbb];
#pragma unroll
                for (int ws = 0; ws < 8; ws++) s += RED[(ws * 64 + r) * GB + sbb];
                gv[gate] = s;
            }
            float gg = ftanh(gv[0]);
            float ii = fsig(gv[1]);
            float ff = fsig(gv[2]);
            float oo = fsig(gv[3]);
            float c  = ff * CC[sjl * GB + sbb] + ii * gg;
            CC[sjl * GB + sbb] = c;
            float h = oo * ftanh(c);
            ghg[((size_t)t * HH + j0 + sjl) * GB + sbb] = h;
        }

        // 4) publish, prefetch next xp under the wait, poll own group's 32 flags
        __syncthreads();
        if (tid == 0) {
            __threadfence();
            flags[blockIdx.x * 32] = ebase + (unsigned)(t + 1);
        }
        if (tid < 128 && t + 1 < TT)
            xpv = __ldcg((const float4*)(xpsrc + (size_t)(t + 1) * G4 * BB));
        if (tid < GSZ) {
            unsigned want = ebase + (unsigned)(t + 1);
            while (flags[(group * GSZ + tid) * 32] < want) { }
        }
        __syncthreads();
    }
}

// ---------------------------------------------------------------------------
// Final FC: out[b][o] = sum_k h_{T-1}[k][b] * fcW[o][k] + fcb[o]
// ---------------------------------------------------------------------------
__global__ void fc_kernel(const float* __restrict__ fcW,
                          const float* __restrict__ fcb,
                          float* __restrict__ out)
{
    const int b = blockIdx.x;
    const int o = threadIdx.x;
    const int g = b >> 3, bb = b & 7;
    __shared__ float hsh[HH];
    for (int k = threadIdx.x; k < HH; k += blockDim.x)
        hsh[k] = g_h[(((size_t)g * TT + TT - 1) * HH + k) * GB + bb];
    __syncthreads();
    float acc = 0.f;
    const float* wv = fcW + (size_t)o * HH;
#pragma unroll 8
    for (int k = 0; k < HH; k += 4) {
        float4 w4 = *(const float4*)(wv + k);
        acc += w4.x * hsh[k] + w4.y * hsh[k + 1] + w4.z * hsh[k + 2] + w4.w * hsh[k + 3];
    }
    out[(size_t)b * OO + o] = acc + fcb[o];
}

// ---------------------------------------------------------------------------
extern "C" void kernel_launch(void* const* d_in, const int* in_sizes, int n_in,
                              void* d_out, int out_size)
{
    const float* x   = (const float*)d_in[0];
    const float* Wx0 = (const float*)d_in[1];
    const float* bx0 = (const float*)d_in[2];
    const float* Wh0 = (const float*)d_in[3];
    const float* bh0 = (const float*)d_in[4];
    const float* Wx1 = (const float*)d_in[5];
    const float* bx1 = (const float*)d_in[6];
    const float* Wh1 = (const float*)d_in[7];
    const float* bh1 = (const float*)d_in[8];
    const float* fcW = (const float*)d_in[9];
    const float* fcb = (const float*)d_in[10];
    float* out = (float*)d_out;
    (void)in_sizes; (void)n_in; (void)out_size;

    float* xp = nullptr; cudaGetSymbolAddress((void**)&xp, g_xp);
    float* gh = nullptr; cudaGetSymbolAddress((void**)&gh, g_h);
    float* wt = nullptr; cudaGetSymbolAddress((void**)&wt, g_wt);

    cudaFuncSetAttribute(lstm_kernel,
                         cudaFuncAttributeMaxDynamicSharedMemorySize,
                         LSTM_SMEM_BYTES);

    dim3 gproj(G4 / 256, MM / 64);

    // ---- Layer 0 ----  (lstm0 at launch index 3 for ncu capture)
    transpose_w_kernel<<<dim3(G4 / 32, DD / 32), 256>>>(Wx0, wt, DD);      // 0
    transpose_x_kernel<<<dim3(TT, DD / 32), 256>>>(x, gh);                 // 1 (+flag reset)
    proj_kernel<<<gproj, 256>>>(wt, bx0, bh0, gh, DD, xp);                 // 2
    lstm_kernel<<<NCTA, 256, LSTM_SMEM_BYTES>>>(Wh0, xp, gh, 0u);          // 3

    // ---- Layer 1 ----
    transpose_w_kernel<<<dim3(G4 / 32, HH / 32), 256>>>(Wx1, wt, HH);      // 4
    proj_kernel<<<gproj, 256>>>(wt, bx1, bh1, gh, HH, xp);                 // 5
    lstm_kernel<<<NCTA, 256, LSTM_SMEM_BYTES>>>(Wh1, xp, gh, (unsigned)TT);// 6

    fc_kernel<<<BB, 256>>>(fcW, fcb, out);                                 // 7
}